// round 2
// baseline (speedup 1.0000x reference)
#include <cuda_runtime.h>
#include <cuda_bf16.h>
#include <cstdint>
#include <cstddef>

#define Bsz 16
#define Cc  512
#define HWn 3136
#define Kw  128

// ---------------- scratch (static __device__, no allocation) ----------------
__device__ float g_phi[Bsz * Kw * HWn];     // phi_xT, [b][k][n], relu'd
__device__ float g_inv[Bsz * HWn];          // 1/sqrt(D+1e-8)
__device__ float g_s[Bsz * Kw];             // column sums of phi_x
__device__ float g_rou[Bsz * Kw];           // sigmoid(rou(pool(y)))
__device__ float g_pooled[Bsz * Cc];
__device__ float g_t[Bsz * Kw * Cc];        // P^T X2
__device__ float g_wneg[Bsz * Kw * Cc];     // -rou * (t @ zeta^T)
__device__ float g_zetaT[Cc * Cc];          // zeta_w transposed: [ci][co]

// ---------------- 1) pooled[b,c] = mean_n y[b,c,n] ----------------
__global__ void pool_kernel(const float* __restrict__ y) {
    int bc = blockIdx.x;                       // 0..B*C-1
    const float4* p4 = (const float4*)(y + (size_t)bc * HWn);
    float sum = 0.f;
    for (int i = threadIdx.x; i < HWn / 4; i += 256) {
        float4 v = p4[i];
        sum += v.x + v.y + v.z + v.w;
    }
    __shared__ float red[8];
    for (int o = 16; o; o >>= 1) sum += __shfl_down_sync(0xffffffffu, sum, o);
    if ((threadIdx.x & 31) == 0) red[threadIdx.x >> 5] = sum;
    __syncthreads();
    if (threadIdx.x < 8) {
        float v = red[threadIdx.x];
        for (int o = 4; o; o >>= 1) v += __shfl_down_sync(0xffu, v, o);
        if (threadIdx.x == 0) g_pooled[bc] = v / (float)HWn;
    }
}

// ---------------- 2) rou_y[b,k] = sigmoid(pooled @ rou_w^T + rou_b) ----------------
__global__ void rou_kernel(const float* __restrict__ rou_w, const float* __restrict__ rou_b) {
    int b = blockIdx.x;
    __shared__ float sp[Cc];
    for (int i = threadIdx.x; i < Cc; i += 128) sp[i] = g_pooled[b * Cc + i];
    __syncthreads();
    int k = threadIdx.x;                       // 128 threads
    const float* wr = rou_w + k * Cc;
    float acc = rou_b[k];
#pragma unroll 8
    for (int c = 0; c < Cc; c++) acc += sp[c] * wr[c];
    g_rou[b * Kw + k] = 1.f / (1.f + __expf(-acc));
}

// ---------------- 3) zetaT[ci][co] = zeta_w[co][ci] ----------------
__global__ void transpose_kernel(const float* __restrict__ zw) {
    __shared__ float tile[32][33];
    int cx = blockIdx.x * 32 + threadIdx.x;    // ci
    int cy = blockIdx.y * 32;                  // co base
    for (int j = 0; j < 32; j += 8)
        tile[threadIdx.y + j][threadIdx.x] = zw[(cy + threadIdx.y + j) * Cc + cx];
    __syncthreads();
    int ox = blockIdx.y * 32 + threadIdx.x;    // co
    int oy = blockIdx.x * 32;                  // ci base
    for (int j = 0; j < 32; j += 8)
        g_zetaT[(oy + threadIdx.y + j) * Cc + ox] = tile[threadIdx.x][threadIdx.y + j];
}

// ---------------- 4) phi GEMM: g_phi[b][k][n] = relu(phi_w @ x[b] + phi_b) ----------------
// M=128(k) x N=3136(n), K=512(c). 128x128 tile, 8x8 micro.
__global__ __launch_bounds__(256) void phi_gemm_kernel(
    const float* __restrict__ x, const float* __restrict__ phi_w, const float* __restrict__ phi_b) {
    int b = blockIdx.y;
    int n0 = blockIdx.x * 128;
    const float* xb = x + (size_t)b * Cc * HWn;
    __shared__ float As[16][128];
    __shared__ float Bs[16][128];
    float acc[8][8] = {};
    int tid = threadIdx.x, tx = tid & 15, ty = tid >> 4;

    for (int k0 = 0; k0 < Cc; k0 += 16) {
        __syncthreads();
        // A: phi_w [128 x 512] row-major -> As[kk][m]
#pragma unroll
        for (int j = 0; j < 2; j++) {
            int f = tid + j * 256;             // 512 float4
            int m = f >> 2, q = f & 3;
            float4 v = *(const float4*)&phi_w[m * Cc + k0 + q * 4];
            As[q * 4 + 0][m] = v.x; As[q * 4 + 1][m] = v.y;
            As[q * 4 + 2][m] = v.z; As[q * 4 + 3][m] = v.w;
        }
        // B: x[b] [512 x 3136] row-major along n -> Bs[kk][n]
#pragma unroll
        for (int j = 0; j < 2; j++) {
            int f = tid + j * 256;
            int kk = f >> 5, n4 = f & 31;
            int n = n0 + n4 * 4;
            float4 v = make_float4(0.f, 0.f, 0.f, 0.f);
            if (n < HWn) v = *(const float4*)&xb[(size_t)(k0 + kk) * HWn + n];
            *(float4*)&Bs[kk][n4 * 4] = v;
        }
        __syncthreads();
#pragma unroll
        for (int kk = 0; kk < 16; kk++) {
            float4 a0 = *(float4*)&As[kk][ty * 4], a1 = *(float4*)&As[kk][64 + ty * 4];
            float4 b0 = *(float4*)&Bs[kk][tx * 4], b1 = *(float4*)&Bs[kk][64 + tx * 4];
            float av[8] = {a0.x, a0.y, a0.z, a0.w, a1.x, a1.y, a1.z, a1.w};
            float bv[8] = {b0.x, b0.y, b0.z, b0.w, b1.x, b1.y, b1.z, b1.w};
#pragma unroll
            for (int i = 0; i < 8; i++)
#pragma unroll
                for (int jj = 0; jj < 8; jj++) acc[i][jj] += av[i] * bv[jj];
        }
    }
    float* outp = g_phi + (size_t)b * Kw * HWn;
#pragma unroll
    for (int i = 0; i < 8; i++) {
        int m = (i < 4) ? ty * 4 + i : 64 + ty * 4 + (i - 4);
        float bias = phi_b[m];
#pragma unroll
        for (int jh = 0; jh < 2; jh++) {
            int n = n0 + (jh ? 64 + tx * 4 : tx * 4);
            if (n < HWn) {
                float4 v;
                v.x = fmaxf(acc[i][jh * 4 + 0] + bias, 0.f);
                v.y = fmaxf(acc[i][jh * 4 + 1] + bias, 0.f);
                v.z = fmaxf(acc[i][jh * 4 + 2] + bias, 0.f);
                v.w = fmaxf(acc[i][jh * 4 + 3] + bias, 0.f);
                *(float4*)&outp[(size_t)m * HWn + n] = v;
            }
        }
    }
}

// ---------------- 5) s[b,k] = sum_n g_phi[b][k][n] ----------------
__global__ void s_kernel() {
    int bk = blockIdx.x;                       // 0..B*Kw-1
    const float4* p4 = (const float4*)(g_phi + (size_t)bk * HWn);
    float sum = 0.f;
    for (int i = threadIdx.x; i < HWn / 4; i += 256) {
        float4 v = p4[i];
        sum += v.x + v.y + v.z + v.w;
    }
    __shared__ float red[8];
    for (int o = 16; o; o >>= 1) sum += __shfl_down_sync(0xffffffffu, sum, o);
    if ((threadIdx.x & 31) == 0) red[threadIdx.x >> 5] = sum;
    __syncthreads();
    if (threadIdx.x < 8) {
        float v = red[threadIdx.x];
        for (int o = 4; o; o >>= 1) v += __shfl_down_sync(0xffu, v, o);
        if (threadIdx.x == 0) g_s[bk] = v;
    }
}

// ---------------- 6) inv_sqrt[b,n] = rsqrt(sum_k phi[k,n]*rou[k]*s[k] + 1e-8) ----------------
__global__ void d_kernel() {
    int b = blockIdx.y;
    __shared__ float coef[Kw];
    if (threadIdx.x < Kw) coef[threadIdx.x] = g_rou[b * Kw + threadIdx.x] * g_s[b * Kw + threadIdx.x];
    __syncthreads();
    int n = blockIdx.x * 256 + threadIdx.x;
    if (n < HWn) {
        const float* p = g_phi + (size_t)b * Kw * HWn + n;
        float acc = 0.f;
#pragma unroll 8
        for (int k = 0; k < Kw; k++) acc += p[(size_t)k * HWn] * coef[k];
        g_inv[b * HWn + n] = rsqrtf(acc + 1e-8f);
    }
}

// ---------------- 7) t GEMM: t[b][k][c] = sum_n (phi[k,n]*inv[n]) * X2[n,c] ----------------
// M=128(k) x N=512(c), K=3136(n). 64x64 tiles, 4x4 micro.
__global__ __launch_bounds__(256) void t_gemm_kernel(const float* __restrict__ x) {
    int b = blockIdx.z, m0 = blockIdx.y * 64, c0 = blockIdx.x * 64;
    const float* phib = g_phi + (size_t)b * Kw * HWn;
    const float* invb = g_inv + b * HWn;
    const float* xb = x + (size_t)b * Cc * HWn;   // viewed [HWn][Cc]
    __shared__ float As[16][64];
    __shared__ float Bs[16][64];
    float acc[4][4] = {};
    int tid = threadIdx.x, tx = tid & 15, ty = tid >> 4;

    for (int kk0 = 0; kk0 < HWn; kk0 += 16) {
        __syncthreads();
        {   // A: phi rows m0..m0+63, cols kk0..kk0+15 (scaled by inv) -> As[kk][m]
            int m = tid >> 2, q = tid & 3;
            float4 v = *(const float4*)&phib[(size_t)(m0 + m) * HWn + kk0 + q * 4];
            float4 iv = *(const float4*)&invb[kk0 + q * 4];
            As[q * 4 + 0][m] = v.x * iv.x; As[q * 4 + 1][m] = v.y * iv.y;
            As[q * 4 + 2][m] = v.z * iv.z; As[q * 4 + 3][m] = v.w * iv.w;
        }
        {   // B: X2 rows kk0+kk, cols c0..c0+63 -> Bs[kk][c]
            int kk = tid >> 4, c4 = tid & 15;
            float4 v = *(const float4*)&xb[(size_t)(kk0 + kk) * Cc + c0 + c4 * 4];
            *(float4*)&Bs[kk][c4 * 4] = v;
        }
        __syncthreads();
#pragma unroll
        for (int kk = 0; kk < 16; kk++) {
            float4 a = *(float4*)&As[kk][ty * 4];
            float4 bb = *(float4*)&Bs[kk][tx * 4];
            float av[4] = {a.x, a.y, a.z, a.w};
            float bv[4] = {bb.x, bb.y, bb.z, bb.w};
#pragma unroll
            for (int i = 0; i < 4; i++)
#pragma unroll
                for (int jj = 0; jj < 4; jj++) acc[i][jj] += av[i] * bv[jj];
        }
    }
    float* tb = g_t + (size_t)b * Kw * Cc;
#pragma unroll
    for (int i = 0; i < 4; i++) {
        int m = m0 + ty * 4 + i;
        float4 v = make_float4(acc[i][0], acc[i][1], acc[i][2], acc[i][3]);
        *(float4*)&tb[(size_t)m * Cc + c0 + tx * 4] = v;
    }
}

// ---------------- 8) w GEMM: wneg[b][k][c] = -rou[b][k] * (t @ zetaT)[k][c] ----------------
// M=128(k) x N=512(co), K=512(ci). 64x64 tiles.
__global__ __launch_bounds__(256) void w_gemm_kernel() {
    int b = blockIdx.z, m0 = blockIdx.y * 64, c0 = blockIdx.x * 64;
    const float* tb = g_t + (size_t)b * Kw * Cc;
    __shared__ float As[16][64];
    __shared__ float Bs[16][64];
    float acc[4][4] = {};
    int tid = threadIdx.x, tx = tid & 15, ty = tid >> 4;

    for (int kk0 = 0; kk0 < Cc; kk0 += 16) {
        __syncthreads();
        {
            int m = tid >> 2, q = tid & 3;
            float4 v = *(const float4*)&tb[(size_t)(m0 + m) * Cc + kk0 + q * 4];
            As[q * 4 + 0][m] = v.x; As[q * 4 + 1][m] = v.y;
            As[q * 4 + 2][m] = v.z; As[q * 4 + 3][m] = v.w;
        }
        {
            int kk = tid >> 4, c4 = tid & 15;
            float4 v = *(const float4*)&g_zetaT[(size_t)(kk0 + kk) * Cc + c0 + c4 * 4];
            *(float4*)&Bs[kk][c4 * 4] = v;
        }
        __syncthreads();
#pragma unroll
        for (int kk = 0; kk < 16; kk++) {
            float4 a = *(float4*)&As[kk][ty * 4];
            float4 bb = *(float4*)&Bs[kk][tx * 4];
            float av[4] = {a.x, a.y, a.z, a.w};
            float bv[4] = {bb.x, bb.y, bb.z, bb.w};
#pragma unroll
            for (int i = 0; i < 4; i++)
#pragma unroll
                for (int jj = 0; jj < 4; jj++) acc[i][jj] += av[i] * bv[jj];
        }
    }
    float* wb = g_wneg + (size_t)b * Kw * Cc;
#pragma unroll
    for (int i = 0; i < 4; i++) {
        int m = m0 + ty * 4 + i;
        float r = -g_rou[b * Kw + m];
        float4 v = make_float4(r * acc[i][0], r * acc[i][1], r * acc[i][2], r * acc[i][3]);
        *(float4*)&wb[(size_t)m * Cc + c0 + tx * 4] = v;
    }
}

// ---------------- 9) fused output GEMM + relu + residual ----------------
// out[n,co] = x.flat + relu( X2[n,:]@zetaT[:,co] + P[n,:]@wneg[:,co] + zeta_b[co] )
// M=3136(n) x N=512(co), K=640 = 512 (X2/zetaT) + 128 (P/wneg). 128x128 tiles.
__global__ __launch_bounds__(256) void out_gemm_kernel(
    const float* __restrict__ x, const float* __restrict__ zeta_b, float* __restrict__ out) {
    int b = blockIdx.z;
    int n0 = blockIdx.x * 128;
    int c0 = blockIdx.y * 128;
    const float* xb = x + (size_t)b * Cc * HWn;
    const float* phib = g_phi + (size_t)b * Kw * HWn;
    const float* invb = g_inv + b * HWn;
    const float* wb = g_wneg + (size_t)b * Kw * Cc;
    __shared__ float As[16][128];
    __shared__ float Bs[16][128];
    float acc[8][8] = {};
    int tid = threadIdx.x, tx = tid & 15, ty = tid >> 4;

    for (int k0 = 0; k0 < 640; k0 += 16) {
        __syncthreads();
        if (k0 < Cc) {
            // A rows from X2 (x flat viewed [HWn][Cc]) -> transpose into As[kk][m]
#pragma unroll
            for (int j = 0; j < 2; j++) {
                int f = tid + j * 256;
                int m = f >> 2, q = f & 3;
                int n = n0 + m;
                float4 v = make_float4(0.f, 0.f, 0.f, 0.f);
                if (n < HWn) v = *(const float4*)&xb[(size_t)n * Cc + k0 + q * 4];
                As[q * 4 + 0][m] = v.x; As[q * 4 + 1][m] = v.y;
                As[q * 4 + 2][m] = v.z; As[q * 4 + 3][m] = v.w;
            }
        } else {
            // A cols from P = phi * inv  (phi is k-major: rows = kg, cols = n)
#pragma unroll
            for (int j = 0; j < 2; j++) {
                int f = tid + j * 256;
                int kk = f >> 5, n4 = f & 31;
                int n = n0 + n4 * 4;
                float4 v = make_float4(0.f, 0.f, 0.f, 0.f);
                if (n < HWn) {
                    v = *(const float4*)&phib[(size_t)(k0 - Cc + kk) * HWn + n];
                    float4 iv = *(const float4*)&invb[n];
                    v.x *= iv.x; v.y *= iv.y; v.z *= iv.z; v.w *= iv.w;
                }
                *(float4*)&As[kk][n4 * 4] = v;
            }
        }
        // B rows: r<512 -> zetaT[r][c], else wneg[r-512][c]
#pragma unroll
        for (int j = 0; j < 2; j++) {
            int f = tid + j * 256;
            int kk = f >> 5, c4 = f & 31;
            int r = k0 + kk;
            const float* src = (r < Cc) ? &g_zetaT[(size_t)r * Cc + c0 + c4 * 4]
                                        : &wb[(size_t)(r - Cc) * Cc + c0 + c4 * 4];
            *(float4*)&Bs[kk][c4 * 4] = *(const float4*)src;
        }
        __syncthreads();
#pragma unroll
        for (int kk = 0; kk < 16; kk++) {
            float4 a0 = *(float4*)&As[kk][ty * 4], a1 = *(float4*)&As[kk][64 + ty * 4];
            float4 b0 = *(float4*)&Bs[kk][tx * 4], b1 = *(float4*)&Bs[kk][64 + tx * 4];
            float av[8] = {a0.x, a0.y, a0.z, a0.w, a1.x, a1.y, a1.z, a1.w};
            float bv[8] = {b0.x, b0.y, b0.z, b0.w, b1.x, b1.y, b1.z, b1.w};
#pragma unroll
            for (int i = 0; i < 8; i++)
#pragma unroll
                for (int jj = 0; jj < 8; jj++) acc[i][jj] += av[i] * bv[jj];
        }
    }
    // epilogue: + zeta_b, relu, + x residual (flat), store
    float bias[8];
#pragma unroll
    for (int j = 0; j < 8; j++) {
        int c = c0 + ((j < 4) ? tx * 4 + j : 64 + tx * 4 + (j - 4));
        bias[j] = zeta_b[c];
    }
    float* outb = out + (size_t)b * Cc * HWn;
#pragma unroll
    for (int i = 0; i < 8; i++) {
        int m = (i < 4) ? ty * 4 + i : 64 + ty * 4 + (i - 4);
        int n = n0 + m;
        if (n >= HWn) continue;
#pragma unroll
        for (int jh = 0; jh < 2; jh++) {
            int c = c0 + (jh ? 64 + tx * 4 : tx * 4);
            size_t idx = (size_t)n * Cc + c;
            float4 xv = *(const float4*)&xb[idx];
            float4 v;
            v.x = xv.x + fmaxf(acc[i][jh * 4 + 0] + bias[jh * 4 + 0], 0.f);
            v.y = xv.y + fmaxf(acc[i][jh * 4 + 1] + bias[jh * 4 + 1], 0.f);
            v.z = xv.z + fmaxf(acc[i][jh * 4 + 2] + bias[jh * 4 + 2], 0.f);
            v.w = xv.w + fmaxf(acc[i][jh * 4 + 3] + bias[jh * 4 + 3], 0.f);
            *(float4*)&outb[idx] = v;
        }
    }
}

// ---------------- launch ----------------
extern "C" void kernel_launch(void* const* d_in, const int* in_sizes, int n_in,
                              void* d_out, int out_size) {
    const float* x      = (const float*)d_in[0];
    const float* y      = (const float*)d_in[1];
    const float* phi_w  = (const float*)d_in[2];
    const float* phi_b  = (const float*)d_in[3];
    const float* rou_w  = (const float*)d_in[4];
    const float* rou_b  = (const float*)d_in[5];
    const float* zeta_w = (const float*)d_in[6];
    const float* zeta_b = (const float*)d_in[7];
    float* out = (float*)d_out;

    pool_kernel<<<Bsz * Cc, 256>>>(y);
    rou_kernel<<<Bsz, 128>>>(rou_w, rou_b);
    transpose_kernel<<<dim3(Cc / 32, Cc / 32), dim3(32, 8)>>>(zeta_w);
    phi_gemm_kernel<<<dim3((HWn + 127) / 128, Bsz), 256>>>(x, phi_w, phi_b);
    s_kernel<<<Bsz * Kw, 256>>>();
    d_kernel<<<dim3((HWn + 255) / 256, Bsz), 256>>>();
    t_gemm_kernel<<<dim3(Cc / 64, Kw / 64, Bsz), 256>>>(x);
    w_gemm_kernel<<<dim3(Cc / 64, Kw / 64, Bsz), 256>>>();
    out_gemm_kernel<<<dim3((HWn + 127) / 128, Cc / 128, Bsz), 256>>>(x, zeta_b, out);
}

// round 5
// speedup vs baseline: 1.4598x; 1.4598x over previous
#include <cuda_runtime.h>
#include <cuda_bf16.h>
#include <mma.h>
#include <cstdint>
#include <cstddef>

using namespace nvcuda;

#define Bsz 16
#define Cc  512
#define HWn 3136
#define Kw  128

typedef wmma::fragment<wmma::matrix_a, 16, 16, 8, wmma::precision::tf32, wmma::row_major> FragA;
typedef wmma::fragment<wmma::matrix_b, 16, 16, 8, wmma::precision::tf32, wmma::row_major> FragB;
typedef wmma::fragment<wmma::accumulator, 16, 16, 8, float> FragC;

// ---------------- scratch (static __device__, no allocation) ----------------
__device__ float g_phi[Bsz * Kw * HWn];     // phi_xT, [b][k][n], relu'd
__device__ float g_inv[Bsz * HWn];          // 1/sqrt(D+1e-8)
__device__ float g_s[Bsz * Kw];             // column sums of phi_x
__device__ float g_rou[Bsz * Kw];           // sigmoid(rou(pool(y)))
__device__ float g_pooled[Bsz * Cc];
__device__ float g_t[Bsz * Kw * Cc];        // P^T X2, split-K part 0
__device__ float g_t2[Bsz * Kw * Cc];       // split-K part 1
__device__ float g_wneg[Bsz * Kw * Cc];     // -rou * (t @ zeta^T)
__device__ float g_zetaT[Cc * Cc];          // zeta_w transposed: [ci][co]

__device__ __forceinline__ float tf32c(float v) { return wmma::__float_to_tf32(v); }

// ---------------- 1) pooled[b,c] = mean_n y[b,c,n] ----------------
__global__ void pool_kernel(const float* __restrict__ y) {
    int bc = blockIdx.x;
    const float4* p4 = (const float4*)(y + (size_t)bc * HWn);
    float sum = 0.f;
    for (int i = threadIdx.x; i < HWn / 4; i += 256) {
        float4 v = p4[i];
        sum += v.x + v.y + v.z + v.w;
    }
    __shared__ float red[8];
    for (int o = 16; o; o >>= 1) sum += __shfl_down_sync(0xffffffffu, sum, o);
    if ((threadIdx.x & 31) == 0) red[threadIdx.x >> 5] = sum;
    __syncthreads();
    if (threadIdx.x < 8) {
        float v = red[threadIdx.x];
        for (int o = 4; o; o >>= 1) v += __shfl_down_sync(0xffu, v, o);
        if (threadIdx.x == 0) g_pooled[bc] = v / (float)HWn;
    }
}

// ---------------- 2) rou_y[b,k] = sigmoid(pooled @ rou_w^T + rou_b) ----------------
__global__ void rou_kernel(const float* __restrict__ rou_w, const float* __restrict__ rou_b) {
    int b = blockIdx.x;
    __shared__ float sp[Cc];
    for (int i = threadIdx.x; i < Cc; i += 128) sp[i] = g_pooled[b * Cc + i];
    __syncthreads();
    int k = threadIdx.x;
    const float* wr = rou_w + k * Cc;
    float acc = rou_b[k];
#pragma unroll 8
    for (int c = 0; c < Cc; c++) acc += sp[c] * wr[c];
    g_rou[b * Kw + k] = 1.f / (1.f + __expf(-acc));
}

// ---------------- 3) zetaT[ci][co] = zeta_w[co][ci] ----------------
__global__ void transpose_kernel(const float* __restrict__ zw) {
    __shared__ float tile[32][33];
    int cx = blockIdx.x * 32 + threadIdx.x;
    int cy = blockIdx.y * 32;
    for (int j = 0; j < 32; j += 8)
        tile[threadIdx.y + j][threadIdx.x] = zw[(cy + threadIdx.y + j) * Cc + cx];
    __syncthreads();
    int ox = blockIdx.y * 32 + threadIdx.x;
    int oy = blockIdx.x * 32;
    for (int j = 0; j < 32; j += 8)
        g_zetaT[(oy + threadIdx.y + j) * Cc + ox] = tile[threadIdx.x][threadIdx.y + j];
}

// ---------------- 4) phi GEMM (TF32 TC): g_phi[b][k][n] = relu(phi_w @ x[b] + phi_b)
// M=128(k) x N=64(n) per block, K=512. grid (49, B).
__global__ __launch_bounds__(256) void phi_gemm_tc(
    const float* __restrict__ x, const float* __restrict__ phi_w, const float* __restrict__ phi_b) {
    __shared__ float buf[8704];                 // max(As+Bs, Cs)
    float* As = buf;                            // [128][36]
    float* Bs = buf + 128 * 36;                 // [32][68]
    int b = blockIdx.y, n0 = blockIdx.x * 64;
    const float* xb = x + (size_t)b * Cc * HWn;
    int tid = threadIdx.x, wid = tid >> 5;
    int wm = wid & 3, wn = wid >> 2;

    FragC acc[2][2];
#pragma unroll
    for (int i = 0; i < 2; i++)
#pragma unroll
        for (int j = 0; j < 2; j++) wmma::fill_fragment(acc[i][j], 0.f);

    for (int k0 = 0; k0 < Cc; k0 += 32) {
        __syncthreads();
#pragma unroll
        for (int j = 0; j < 4; j++) {           // As: 128x32, k contiguous
            int f = tid + j * 256;
            int m = f >> 3, q = f & 7;
            float4 v = *(const float4*)&phi_w[m * Cc + k0 + q * 4];
            float* d = &As[m * 36 + q * 4];
            d[0] = tf32c(v.x); d[1] = tf32c(v.y); d[2] = tf32c(v.z); d[3] = tf32c(v.w);
        }
#pragma unroll
        for (int j = 0; j < 2; j++) {           // Bs: 32x64, n contiguous
            int f = tid + j * 256;
            int kk = f >> 4, n4 = f & 15;
            float4 v = *(const float4*)&xb[(size_t)(k0 + kk) * HWn + n0 + n4 * 4];
            float* d = &Bs[kk * 68 + n4 * 4];
            d[0] = tf32c(v.x); d[1] = tf32c(v.y); d[2] = tf32c(v.z); d[3] = tf32c(v.w);
        }
        __syncthreads();
#pragma unroll
        for (int kk8 = 0; kk8 < 4; kk8++) {
            FragA a[2]; FragB bf[2];
#pragma unroll
            for (int i = 0; i < 2; i++)
                wmma::load_matrix_sync(a[i], &As[(wm * 32 + i * 16) * 36 + kk8 * 8], 36);
#pragma unroll
            for (int j = 0; j < 2; j++)
                wmma::load_matrix_sync(bf[j], &Bs[(kk8 * 8) * 68 + wn * 32 + j * 16], 68);
#pragma unroll
            for (int i = 0; i < 2; i++)
#pragma unroll
                for (int j = 0; j < 2; j++) wmma::mma_sync(acc[i][j], a[i], bf[j], acc[i][j]);
        }
    }
    __syncthreads();
    float* Cs = buf;                            // [128][68]
#pragma unroll
    for (int i = 0; i < 2; i++)
#pragma unroll
        for (int j = 0; j < 2; j++)
            wmma::store_matrix_sync(&Cs[(wm * 32 + i * 16) * 68 + wn * 32 + j * 16],
                                    acc[i][j], 68, wmma::mem_row_major);
    __syncthreads();
    float* outp = g_phi + (size_t)b * Kw * HWn;
#pragma unroll
    for (int j = 0; j < 8; j++) {
        int f = tid + j * 256;
        int m = f >> 4, c4 = f & 15;
        float bias = phi_b[m];
        const float* s = &Cs[m * 68 + c4 * 4];
        float4 v;
        v.x = fmaxf(s[0] + bias, 0.f); v.y = fmaxf(s[1] + bias, 0.f);
        v.z = fmaxf(s[2] + bias, 0.f); v.w = fmaxf(s[3] + bias, 0.f);
        *(float4*)&outp[(size_t)m * HWn + n0 + c4 * 4] = v;
    }
}

// ---------------- 5) s[b,k] = sum_n g_phi[b][k][n] ----------------
__global__ void s_kernel() {
    int bk = blockIdx.x;
    const float4* p4 = (const float4*)(g_phi + (size_t)bk * HWn);
    float sum = 0.f;
    for (int i = threadIdx.x; i < HWn / 4; i += 256) {
        float4 v = p4[i];
        sum += v.x + v.y + v.z + v.w;
    }
    __shared__ float red[8];
    for (int o = 16; o; o >>= 1) sum += __shfl_down_sync(0xffffffffu, sum, o);
    if ((threadIdx.x & 31) == 0) red[threadIdx.x >> 5] = sum;
    __syncthreads();
    if (threadIdx.x < 8) {
        float v = red[threadIdx.x];
        for (int o = 4; o; o >>= 1) v += __shfl_down_sync(0xffu, v, o);
        if (threadIdx.x == 0) g_s[bk] = v;
    }
}

// ---------------- 6) inv_sqrt[b,n] ----------------
__global__ void d_kernel() {
    int b = blockIdx.y;
    __shared__ float coef[Kw];
    if (threadIdx.x < Kw) coef[threadIdx.x] = g_rou[b * Kw + threadIdx.x] * g_s[b * Kw + threadIdx.x];
    __syncthreads();
    int n = blockIdx.x * 256 + threadIdx.x;
    if (n < HWn) {
        const float* p = g_phi + (size_t)b * Kw * HWn + n;
        float acc = 0.f;
#pragma unroll 8
        for (int k = 0; k < Kw; k++) acc += p[(size_t)k * HWn] * coef[k];
        g_inv[b * HWn + n] = rsqrtf(acc + 1e-8f);
    }
}

// ---------------- 7) t GEMM (TF32 TC, split-K=2): t[b][k][c] = sum_n P[k,n] X2[n,c]
// M=128(k) x N=64(c) per block, K=1568 per split. grid (8, 2, B).
__global__ __launch_bounds__(256) void t_gemm_tc(const float* __restrict__ x) {
    __shared__ float buf[6784];
    float* As = buf;                            // [128][36]
    float* Bs = buf + 128 * 36;                 // [32][68]
    int c0 = blockIdx.x * 64, split = blockIdx.y, b = blockIdx.z;
    const float* phib = g_phi + (size_t)b * Kw * HWn;
    const float* invb = g_inv + b * HWn;
    const float* xb = x + (size_t)b * Cc * HWn; // viewed [HWn][Cc]
    int tid = threadIdx.x, wid = tid >> 5;
    int wm = wid & 3, wn = wid >> 2;

    FragC acc[2][2];
#pragma unroll
    for (int i = 0; i < 2; i++)
#pragma unroll
        for (int j = 0; j < 2; j++) wmma::fill_fragment(acc[i][j], 0.f);

    int nbase = split * 1568;
    for (int ch = 0; ch < 49; ch++) {
        int nb = nbase + ch * 32;
        __syncthreads();
#pragma unroll
        for (int j = 0; j < 4; j++) {           // As[k][n-chunk] = phi * inv, n contiguous
            int f = tid + j * 256;
            int m = f >> 3, q = f & 7;
            float4 v = *(const float4*)&phib[(size_t)m * HWn + nb + q * 4];
            float4 iv = *(const float4*)&invb[nb + q * 4];
            float* d = &As[m * 36 + q * 4];
            d[0] = tf32c(v.x * iv.x); d[1] = tf32c(v.y * iv.y);
            d[2] = tf32c(v.z * iv.z); d[3] = tf32c(v.w * iv.w);
        }
#pragma unroll
        for (int j = 0; j < 2; j++) {           // Bs[n-chunk][c], c contiguous
            int f = tid + j * 256;
            int kk = f >> 4, c4 = f & 15;
            float4 v = *(const float4*)&xb[(size_t)(nb + kk) * Cc + c0 + c4 * 4];
            float* d = &Bs[kk * 68 + c4 * 4];
            d[0] = tf32c(v.x); d[1] = tf32c(v.y); d[2] = tf32c(v.z); d[3] = tf32c(v.w);
        }
        __syncthreads();
#pragma unroll
        for (int kk8 = 0; kk8 < 4; kk8++) {
            FragA a[2]; FragB bf[2];
#pragma unroll
            for (int i = 0; i < 2; i++)
                wmma::load_matrix_sync(a[i], &As[(wm * 32 + i * 16) * 36 + kk8 * 8], 36);
#pragma unroll
            for (int j = 0; j < 2; j++)
                wmma::load_matrix_sync(bf[j], &Bs[(kk8 * 8) * 68 + wn * 32 + j * 16], 68);
#pragma unroll
            for (int i = 0; i < 2; i++)
#pragma unroll
                for (int j = 0; j < 2; j++) wmma::mma_sync(acc[i][j], a[i], bf[j], acc[i][j]);
        }
    }
    float* tb = (split ? g_t2 : g_t) + (size_t)b * Kw * Cc;
#pragma unroll
    for (int i = 0; i < 2; i++)
#pragma unroll
        for (int j = 0; j < 2; j++)
            wmma::store_matrix_sync(&tb[(size_t)(wm * 32 + i * 16) * Cc + c0 + wn * 32 + j * 16],
                                    acc[i][j], Cc, wmma::mem_row_major);
}

// ---------------- 8) w GEMM: wneg[b][k][c] = -rou[b][k] * ((t0+t1) @ zetaT)[k][c] ----------------
__global__ __launch_bounds__(256) void w_gemm_kernel() {
    int b = blockIdx.z, m0 = blockIdx.y * 64, c0 = blockIdx.x * 64;
    const float* tb = g_t + (size_t)b * Kw * Cc;
    const float* tb2 = g_t2 + (size_t)b * Kw * Cc;
    __shared__ float As[16][64];
    __shared__ float Bs[16][64];
    float acc[4][4] = {};
    int tid = threadIdx.x, tx = tid & 15, ty = tid >> 4;

    for (int kk0 = 0; kk0 < Cc; kk0 += 16) {
        __syncthreads();
        {
            int m = tid >> 2, q = tid & 3;
            size_t off = (size_t)(m0 + m) * Cc + kk0 + q * 4;
            float4 v = *(const float4*)&tb[off];
            float4 v2 = *(const float4*)&tb2[off];
            As[q * 4 + 0][m] = v.x + v2.x; As[q * 4 + 1][m] = v.y + v2.y;
            As[q * 4 + 2][m] = v.z + v2.z; As[q * 4 + 3][m] = v.w + v2.w;
        }
        {
            int kk = tid >> 4, c4 = tid & 15;
            float4 v = *(const float4*)&g_zetaT[(size_t)(kk0 + kk) * Cc + c0 + c4 * 4];
            *(float4*)&Bs[kk][c4 * 4] = v;
        }
        __syncthreads();
#pragma unroll
        for (int kk = 0; kk < 16; kk++) {
            float4 a = *(float4*)&As[kk][ty * 4];
            float4 bb = *(float4*)&Bs[kk][tx * 4];
            float av[4] = {a.x, a.y, a.z, a.w};
            float bv[4] = {bb.x, bb.y, bb.z, bb.w};
#pragma unroll
            for (int i = 0; i < 4; i++)
#pragma unroll
                for (int jj = 0; jj < 4; jj++) acc[i][jj] += av[i] * bv[jj];
        }
    }
    float* wb = g_wneg + (size_t)b * Kw * Cc;
#pragma unroll
    for (int i = 0; i < 4; i++) {
        int m = m0 + ty * 4 + i;
        float r = -g_rou[b * Kw + m];
        float4 v = make_float4(r * acc[i][0], r * acc[i][1], r * acc[i][2], r * acc[i][3]);
        *(float4*)&wb[(size_t)m * Cc + c0 + tx * 4] = v;
    }
}

// ---------------- 9) fused output GEMM (TF32 TC) + relu + residual ----------------
// out[n,co] = x + relu( [X2|P][n,:] @ [zetaT; wneg][:,co] + zeta_b[co] )
// M=64(n) x N=128(co) per block, K=640. grid (49, 4, B).
__global__ __launch_bounds__(256) void out_gemm_tc(
    const float* __restrict__ x, const float* __restrict__ zeta_b, float* __restrict__ out) {
    __shared__ float buf[8448];
    float* As = buf;                            // [64][36]
    float* Bs = buf + 64 * 36;                  // [32][132]
    int n0 = blockIdx.x * 64, c0 = blockIdx.y * 128, b = blockIdx.z;
    const float* xb = x + (size_t)b * Cc * HWn;
    const float* phib = g_phi + (size_t)b * Kw * HWn;
    const float* invb = g_inv + b * HWn;
    const float* wb = g_wneg + (size_t)b * Kw * Cc;
    int tid = threadIdx.x, wid = tid >> 5;
    int wm = wid & 1, wn = wid >> 1;            // 2 x 4 warps, each 32x32

    FragC acc[2][2];
#pragma unroll
    for (int i = 0; i < 2; i++)
#pragma unroll
        for (int j = 0; j < 2; j++) wmma::fill_fragment(acc[i][j], 0.f);

    for (int k0 = 0; k0 < 640; k0 += 32) {
        __syncthreads();
        if (k0 < Cc) {
            // A from X2 (x flat, k contiguous)
#pragma unroll
            for (int j = 0; j < 2; j++) {
                int f = tid + j * 256;
                int m = f >> 3, q = f & 7;
                float4 v = *(const float4*)&xb[(size_t)(n0 + m) * Cc + k0 + q * 4];
                float* d = &As[m * 36 + q * 4];
                d[0] = tf32c(v.x); d[1] = tf32c(v.y); d[2] = tf32c(v.z); d[3] = tf32c(v.w);
            }
        } else {
            // A from P = phi * inv (phi k-major: n contiguous -> transpose into As)
#pragma unroll
            for (int j = 0; j < 2; j++) {
                int f = tid + j * 256;
                int kk = f >> 4, n4 = f & 15;
                float4 v = *(const float4*)&phib[(size_t)(k0 - Cc + kk) * HWn + n0 + n4 * 4];
                float4 iv = *(const float4*)&invb[n0 + n4 * 4];
                As[(n4 * 4 + 0) * 36 + kk] = tf32c(v.x * iv.x);
                As[(n4 * 4 + 1) * 36 + kk] = tf32c(v.y * iv.y);
                As[(n4 * 4 + 2) * 36 + kk] = tf32c(v.z * iv.z);
                As[(n4 * 4 + 3) * 36 + kk] = tf32c(v.w * iv.w);
            }
        }
        // B rows: r<512 -> zetaT, else wneg
#pragma unroll
        for (int j = 0; j < 4; j++) {
            int f = tid + j * 256;
            int kk = f >> 5, c4 = f & 31;
            int r = k0 + kk;
            const float* src = (r < Cc) ? &g_zetaT[(size_t)r * Cc + c0 + c4 * 4]
                                        : &wb[(size_t)(r - Cc) * Cc + c0 + c4 * 4];
            float4 v = *(const float4*)src;
            float* d = &Bs[kk * 132 + c4 * 4];
            d[0] = tf32c(v.x); d[1] = tf32c(v.y); d[2] = tf32c(v.z); d[3] = tf32c(v.w);
        }
        __syncthreads();
#pragma unroll
        for (int kk8 = 0; kk8 < 4; kk8++) {
            FragA a[2]; FragB bf[2];
#pragma unroll
            for (int i = 0; i < 2; i++)
                wmma::load_matrix_sync(a[i], &As[(wm * 32 + i * 16) * 36 + kk8 * 8], 36);
#pragma unroll
            for (int j = 0; j < 2; j++)
                wmma::load_matrix_sync(bf[j], &Bs[(kk8 * 8) * 132 + wn * 32 + j * 16], 132);
#pragma unroll
            for (int i = 0; i < 2; i++)
#pragma unroll
                for (int j = 0; j < 2; j++) wmma::mma_sync(acc[i][j], a[i], bf[j], acc[i][j]);
        }
    }
    __syncthreads();
    float* Cs = buf;                            // [64][132]
#pragma unroll
    for (int i = 0; i < 2; i++)
#pragma unroll
        for (int j = 0; j < 2; j++)
            wmma::store_matrix_sync(&Cs[(wm * 32 + i * 16) * 132 + wn * 32 + j * 16],
                                    acc[i][j], 132, wmma::mem_row_major);
    __syncthreads();
    float* outb = out + (size_t)b * Cc * HWn;
#pragma unroll
    for (int j = 0; j < 8; j++) {
        int f = tid + j * 256;
        int m = f >> 5, c4 = f & 31;
        int c = c0 + c4 * 4;
        size_t idx = (size_t)(n0 + m) * Cc + c;
        float4 xv = *(const float4*)&xb[idx];
        float4 bz = *(const float4*)&zeta_b[c];
        const float* s = &Cs[m * 132 + c4 * 4];
        float4 v;
        v.x = xv.x + fmaxf(s[0] + bz.x, 0.f);
        v.y = xv.y + fmaxf(s[1] + bz.y, 0.f);
        v.z = xv.z + fmaxf(s[2] + bz.z, 0.f);
        v.w = xv.w + fmaxf(s[3] + bz.w, 0.f);
        *(float4*)&outb[idx] = v;
    }
}

// ---------------- launch ----------------
extern "C" void kernel_launch(void* const* d_in, const int* in_sizes, int n_in,
                              void* d_out, int out_size) {
    const float* x      = (const float*)d_in[0];
    const float* y      = (const float*)d_in[1];
    const float* phi_w  = (const float*)d_in[2];
    const float* phi_b  = (const float*)d_in[3];
    const float* rou_w  = (const float*)d_in[4];
    const float* rou_b  = (const float*)d_in[5];
    const float* zeta_w = (const float*)d_in[6];
    const float* zeta_b = (const float*)d_in[7];
    float* out = (float*)d_out;

    pool_kernel<<<Bsz * Cc, 256>>>(y);
    rou_kernel<<<Bsz, 128>>>(rou_w, rou_b);
    transpose_kernel<<<dim3(Cc / 32, Cc / 32), dim3(32, 8)>>>(zeta_w);
    phi_gemm_tc<<<dim3(49, Bsz), 256>>>(x, phi_w, phi_b);
    s_kernel<<<Bsz * Kw, 256>>>();
    d_kernel<<<dim3((HWn + 255) / 256, Bsz), 256>>>();
    t_gemm_tc<<<dim3(Cc / 64, 2, Bsz), 256>>>(x);
    w_gemm_kernel<<<dim3(Cc / 64, Kw / 64, Bsz), 256>>>();
    out_gemm_tc<<<dim3(49, Cc / 128, Bsz), 256>>>(x, zeta_b, out);
}

// round 8
// speedup vs baseline: 1.4969x; 1.0254x over previous
#include <cuda_runtime.h>
#include <cuda_bf16.h>
#include <mma.h>
#include <cstdint>
#include <cstddef>

using namespace nvcuda;

#define Bsz 16
#define Cc  512
#define HWn 3136
#define Kw  128

typedef wmma::fragment<wmma::matrix_a, 16, 16, 8, wmma::precision::tf32, wmma::row_major> FragA;
typedef wmma::fragment<wmma::matrix_b, 16, 16, 8, wmma::precision::tf32, wmma::row_major> FragB;
typedef wmma::fragment<wmma::accumulator, 16, 16, 8, float> FragC;

// ---------------- scratch ----------------
__device__ float g_phi[Bsz * Kw * HWn];     // relu(phi_w@x+b), [b][k][n]
__device__ float g_P[Bsz * Kw * HWn];       // P = phi*inv, [b][k][n]
__device__ float g_Pt[Bsz * HWn * Kw];      // P transposed, [b][n][k]
__device__ float g_inv[Bsz * HWn];
__device__ float g_s[Bsz * Kw];
__device__ float g_rou[Bsz * Kw];
__device__ float g_pooled[Bsz * Cc];
__device__ float g_t[Bsz * Kw * Cc];
__device__ float g_t2[Bsz * Kw * Cc];
__device__ float g_wneg[Bsz * Kw * Cc];
__device__ float g_zetaT[Cc * Cc];

// ---------------- cp.async helpers ----------------
__device__ __forceinline__ uint32_t s2u(const void* p) {
    return (uint32_t)__cvta_generic_to_shared(p);
}
__device__ __forceinline__ void cpa16(uint32_t dst, const void* src) {
    asm volatile("cp.async.cg.shared.global [%0], [%1], 16;\n" :: "r"(dst), "l"(src));
}
__device__ __forceinline__ void cpa16z(uint32_t dst, const void* src, bool valid) {
    int sz = valid ? 16 : 0;
    asm volatile("cp.async.cg.shared.global [%0], [%1], 16, %2;\n" :: "r"(dst), "l"(src), "r"(sz));
}
#define CP_COMMIT() asm volatile("cp.async.commit_group;\n")
#define CP_WAIT(n)  asm volatile("cp.async.wait_group %0;\n" :: "n"(n))

// ---------------- 1) pooled ----------------
__global__ void pool_kernel(const float* __restrict__ y) {
    int bc = blockIdx.x;
    const float4* p4 = (const float4*)(y + (size_t)bc * HWn);
    float sum = 0.f;
    for (int i = threadIdx.x; i < HWn / 4; i += 256) {
        float4 v = p4[i];
        sum += v.x + v.y + v.z + v.w;
    }
    __shared__ float red[8];
    for (int o = 16; o; o >>= 1) sum += __shfl_down_sync(0xffffffffu, sum, o);
    if ((threadIdx.x & 31) == 0) red[threadIdx.x >> 5] = sum;
    __syncthreads();
    if (threadIdx.x < 8) {
        float v = red[threadIdx.x];
        for (int o = 4; o; o >>= 1) v += __shfl_down_sync(0xffu, v, o);
        if (threadIdx.x == 0) g_pooled[bc] = v / (float)HWn;
    }
}

// ---------------- 2) rou ----------------
__global__ void rou_kernel(const float* __restrict__ rou_w, const float* __restrict__ rou_b) {
    int b = blockIdx.x;
    __shared__ float sp[Cc];
    for (int i = threadIdx.x; i < Cc; i += 128) sp[i] = g_pooled[b * Cc + i];
    __syncthreads();
    int k = threadIdx.x;
    const float* wr = rou_w + k * Cc;
    float acc = rou_b[k];
#pragma unroll 8
    for (int c = 0; c < Cc; c++) acc += sp[c] * wr[c];
    g_rou[b * Kw + k] = 1.f / (1.f + __expf(-acc));
}

// ---------------- 3) zetaT ----------------
__global__ void transpose_kernel(const float* __restrict__ zw) {
    __shared__ float tile[32][33];
    int cx = blockIdx.x * 32 + threadIdx.x;
    int cy = blockIdx.y * 32;
    for (int j = 0; j < 32; j += 8)
        tile[threadIdx.y + j][threadIdx.x] = zw[(cy + threadIdx.y + j) * Cc + cx];
    __syncthreads();
    int ox = blockIdx.y * 32 + threadIdx.x;
    int oy = blockIdx.x * 32;
    for (int j = 0; j < 32; j += 8)
        g_zetaT[(oy + threadIdx.y + j) * Cc + ox] = tile[threadIdx.x][threadIdx.y + j];
}

// ---------------- 4) phi GEMM (TF32 TC + cp.async double buffer) ----------------
// M=128(k) x N=128(n), K=512. grid (25, B). tile edge guarded.
#define PHI_AF (128 * 36)
#define PHI_BF (32 * 132)
#define PHI_STG (PHI_AF + PHI_BF)
__global__ __launch_bounds__(256) void phi_gemm_tc2(
    const float* __restrict__ x, const float* __restrict__ phi_w, const float* __restrict__ phi_b) {
    extern __shared__ float sm[];
    int b = blockIdx.y, n0 = blockIdx.x * 128;
    const float* xb = x + (size_t)b * Cc * HWn;
    int tid = threadIdx.x, wid = tid >> 5;
    int wm = wid & 1, wn = wid >> 1;

    FragC acc[4][2];
#pragma unroll
    for (int i = 0; i < 4; i++)
#pragma unroll
        for (int j = 0; j < 2; j++) wmma::fill_fragment(acc[i][j], 0.f);

    auto prefetch = [&](int ch, int st) {
        float* A = sm + st * PHI_STG;
        float* B = A + PHI_AF;
        int k0 = ch * 32;
#pragma unroll
        for (int j = 0; j < 4; j++) {                  // A: phi_w 128x32
            int f = tid + j * 256;
            int m = f >> 3, q = f & 7;
            cpa16(s2u(&A[m * 36 + q * 4]), &phi_w[m * Cc + k0 + q * 4]);
        }
#pragma unroll
        for (int j = 0; j < 4; j++) {                  // B: x 32x128
            int f = tid + j * 256;
            int kk = f >> 5, n4 = f & 31;
            int n = n0 + n4 * 4;
            cpa16z(s2u(&B[kk * 132 + n4 * 4]), &xb[(size_t)(k0 + kk) * HWn + n], n < HWn);
        }
        CP_COMMIT();
    };

    prefetch(0, 0);
    const int NCH = Cc / 32;
    for (int ch = 0; ch < NCH; ch++) {
        if (ch + 1 < NCH) { prefetch(ch + 1, (ch + 1) & 1); CP_WAIT(1); }
        else CP_WAIT(0);
        __syncthreads();
        float* A = sm + (ch & 1) * PHI_STG;
        float* B = A + PHI_AF;
#pragma unroll
        for (int kk8 = 0; kk8 < 4; kk8++) {
            FragA a[4]; FragB bf[2];
#pragma unroll
            for (int i = 0; i < 4; i++)
                wmma::load_matrix_sync(a[i], &A[(wm * 64 + i * 16) * 36 + kk8 * 8], 36);
#pragma unroll
            for (int j = 0; j < 2; j++)
                wmma::load_matrix_sync(bf[j], &B[(kk8 * 8) * 132 + wn * 32 + j * 16], 132);
#pragma unroll
            for (int i = 0; i < 4; i++)
#pragma unroll
                for (int j = 0; j < 2; j++) wmma::mma_sync(acc[i][j], a[i], bf[j], acc[i][j]);
        }
        __syncthreads();
    }
    float* Cs = sm;                                     // [128][132]
#pragma unroll
    for (int i = 0; i < 4; i++)
#pragma unroll
        for (int j = 0; j < 2; j++)
            wmma::store_matrix_sync(&Cs[(wm * 64 + i * 16) * 132 + wn * 32 + j * 16],
                                    acc[i][j], 132, wmma::mem_row_major);
    __syncthreads();
    float* outp = g_phi + (size_t)b * Kw * HWn;
#pragma unroll
    for (int j = 0; j < 16; j++) {
        int f = tid + j * 256;
        int m = f >> 5, c4 = f & 31;
        int n = n0 + c4 * 4;
        if (n < HWn) {
            float bias = phi_b[m];
            const float* s = &Cs[m * 132 + c4 * 4];
            float4 v;
            v.x = fmaxf(s[0] + bias, 0.f); v.y = fmaxf(s[1] + bias, 0.f);
            v.z = fmaxf(s[2] + bias, 0.f); v.w = fmaxf(s[3] + bias, 0.f);
            *(float4*)&outp[(size_t)m * HWn + n] = v;
        }
    }
}

// ---------------- 5) s ----------------
__global__ void s_kernel() {
    int bk = blockIdx.x;
    const float4* p4 = (const float4*)(g_phi + (size_t)bk * HWn);
    float sum = 0.f;
    for (int i = threadIdx.x; i < HWn / 4; i += 256) {
        float4 v = p4[i];
        sum += v.x + v.y + v.z + v.w;
    }
    __shared__ float red[8];
    for (int o = 16; o; o >>= 1) sum += __shfl_down_sync(0xffffffffu, sum, o);
    if ((threadIdx.x & 31) == 0) red[threadIdx.x >> 5] = sum;
    __syncthreads();
    if (threadIdx.x < 8) {
        float v = red[threadIdx.x];
        for (int o = 4; o; o >>= 1) v += __shfl_down_sync(0xffu, v, o);
        if (threadIdx.x == 0) g_s[bk] = v;
    }
}

// ---------------- 6) inv ----------------
__global__ void d_kernel() {
    int b = blockIdx.y;
    __shared__ float coef[Kw];
    if (threadIdx.x < Kw) coef[threadIdx.x] = g_rou[b * Kw + threadIdx.x] * g_s[b * Kw + threadIdx.x];
    __syncthreads();
    int n = blockIdx.x * 256 + threadIdx.x;
    if (n < HWn) {
        const float* p = g_phi + (size_t)b * Kw * HWn + n;
        float acc = 0.f;
#pragma unroll 8
        for (int k = 0; k < Kw; k++) acc += p[(size_t)k * HWn] * coef[k];
        g_inv[b * HWn + n] = rsqrtf(acc + 1e-8f);
    }
}

// ---------------- 6b) P in two layouts: g_P[k][n] and g_Pt[n][k] ----------------
// grid (98, 4, B), block (32, 8)
__global__ void ps_kernel() {
    int n0 = blockIdx.x * 32, k0 = blockIdx.y * 32, b = blockIdx.z;
    const float* phib = g_phi + (size_t)b * Kw * HWn;
    float* pb = g_P + (size_t)b * Kw * HWn;
    __shared__ float tile[32][33];
    float inv = g_inv[b * HWn + n0 + threadIdx.x];
#pragma unroll
    for (int j = 0; j < 32; j += 8) {
        int k = k0 + threadIdx.y + j;
        float v = phib[(size_t)k * HWn + n0 + threadIdx.x] * inv;
        pb[(size_t)k * HWn + n0 + threadIdx.x] = v;
        tile[threadIdx.y + j][threadIdx.x] = v;
    }
    __syncthreads();
    float* ptb = g_Pt + (size_t)b * HWn * Kw;
#pragma unroll
    for (int j = 0; j < 32; j += 8) {
        int n = n0 + threadIdx.y + j;
        ptb[(size_t)n * Kw + k0 + threadIdx.x] = tile[threadIdx.x][threadIdx.y + j];
    }
}

// ---------------- 7) t GEMM (TF32 TC + cp.async, split-K=2) ----------------
// M=128(k) x N=64(c), K=1568 per split. grid (8, 2, B).
#define T_AF (128 * 36)
#define T_BF (32 * 68)
#define T_STG (T_AF + T_BF)
__global__ __launch_bounds__(256) void t_gemm_tc2(const float* __restrict__ x) {
    extern __shared__ float sm[];
    int c0 = blockIdx.x * 64, split = blockIdx.y, b = blockIdx.z;
    const float* pb = g_P + (size_t)b * Kw * HWn;
    const float* xb = x + (size_t)b * Cc * HWn;        // [HWn][Cc]
    int tid = threadIdx.x, wid = tid >> 5;
    int wm = wid & 3, wn = wid >> 2;
    int nbase = split * 1568;

    FragC acc[2][2];
#pragma unroll
    for (int i = 0; i < 2; i++)
#pragma unroll
        for (int j = 0; j < 2; j++) wmma::fill_fragment(acc[i][j], 0.f);

    auto prefetch = [&](int ch, int st) {
        float* A = sm + st * T_STG;
        float* B = A + T_AF;
        int nb = nbase + ch * 32;
#pragma unroll
        for (int j = 0; j < 4; j++) {                  // A: P 128x32 (rows k, contig n)
            int f = tid + j * 256;
            int m = f >> 3, q = f & 7;
            cpa16(s2u(&A[m * 36 + q * 4]), &pb[(size_t)m * HWn + nb + q * 4]);
        }
#pragma unroll
        for (int j = 0; j < 2; j++) {                  // B: X2 32x64
            int f = tid + j * 256;
            int kk = f >> 4, c4 = f & 15;
            cpa16(s2u(&B[kk * 68 + c4 * 4]), &xb[(size_t)(nb + kk) * Cc + c0 + c4 * 4]);
        }
        CP_COMMIT();
    };

    prefetch(0, 0);
    const int NCH = 49;
    for (int ch = 0; ch < NCH; ch++) {
        if (ch + 1 < NCH) { prefetch(ch + 1, (ch + 1) & 1); CP_WAIT(1); }
        else CP_WAIT(0);
        __syncthreads();
        float* A = sm + (ch & 1) * T_STG;
        float* B = A + T_AF;
#pragma unroll
        for (int kk8 = 0; kk8 < 4; kk8++) {
            FragA a[2]; FragB bf[2];
#pragma unroll
            for (int i = 0; i < 2; i++)
                wmma::load_matrix_sync(a[i], &A[(wm * 32 + i * 16) * 36 + kk8 * 8], 36);
#pragma unroll
            for (int j = 0; j < 2; j++)
                wmma::load_matrix_sync(bf[j], &B[(kk8 * 8) * 68 + wn * 32 + j * 16], 68);
#pragma unroll
            for (int i = 0; i < 2; i++)
#pragma unroll
                for (int j = 0; j < 2; j++) wmma::mma_sync(acc[i][j], a[i], bf[j], acc[i][j]);
        }
        __syncthreads();
    }
    float* tb = (split ? g_t2 : g_t) + (size_t)b * Kw * Cc;
#pragma unroll
    for (int i = 0; i < 2; i++)
#pragma unroll
        for (int j = 0; j < 2; j++)
            wmma::store_matrix_sync(&tb[(size_t)(wm * 32 + i * 16) * Cc + c0 + wn * 32 + j * 16],
                                    acc[i][j], Cc, wmma::mem_row_major);
}

// ---------------- 8) w GEMM (SIMT, small) ----------------
__global__ __launch_bounds__(256) void w_gemm_kernel() {
    int b = blockIdx.z, m0 = blockIdx.y * 64, c0 = blockIdx.x * 64;
    const float* tb = g_t + (size_t)b * Kw * Cc;
    const float* tb2 = g_t2 + (size_t)b * Kw * Cc;
    __shared__ float As[16][64];
    __shared__ float Bs[16][64];
    float acc[4][4] = {};
    int tid = threadIdx.x, tx = tid & 15, ty = tid >> 4;

    for (int kk0 = 0; kk0 < Cc; kk0 += 16) {
        __syncthreads();
        {
            int m = tid >> 2, q = tid & 3;
            size_t off = (size_t)(m0 + m) * Cc + kk0 + q * 4;
            float4 v = *(const float4*)&tb[off];
            float4 v2 = *(const float4*)&tb2[off];
            As[q * 4 + 0][m] = v.x + v2.x; As[q * 4 + 1][m] = v.y + v2.y;
            As[q * 4 + 2][m] = v.z + v2.z; As[q * 4 + 3][m] = v.w + v2.w;
        }
        {
            int kk = tid >> 4, c4 = tid & 15;
            float4 v = *(const float4*)&g_zetaT[(size_t)(kk0 + kk) * Cc + c0 + c4 * 4];
            *(float4*)&Bs[kk][c4 * 4] = v;
        }
        __syncthreads();
#pragma unroll
        for (int kk = 0; kk < 16; kk++) {
            float4 a = *(float4*)&As[kk][ty * 4];
            float4 bb = *(float4*)&Bs[kk][tx * 4];
            float av[4] = {a.x, a.y, a.z, a.w};
            float bv[4] = {bb.x, bb.y, bb.z, bb.w};
#pragma unroll
            for (int i = 0; i < 4; i++)
#pragma unroll
                for (int jj = 0; jj < 4; jj++) acc[i][jj] += av[i] * bv[jj];
        }
    }
    float* wb = g_wneg + (size_t)b * Kw * Cc;
#pragma unroll
    for (int i = 0; i < 4; i++) {
        int m = m0 + ty * 4 + i;
        float r = -g_rou[b * Kw + m];
        float4 v = make_float4(r * acc[i][0], r * acc[i][1], r * acc[i][2], r * acc[i][3]);
        *(float4*)&wb[(size_t)m * Cc + c0 + tx * 4] = v;
    }
}

// ---------------- 9) fused out GEMM (TF32 TC + cp.async) ----------------
// M=128(n) x N=128(co), K=640. grid (25, 4, B).
#define O_AF (128 * 36)
#define O_BF (32 * 132)
#define O_STG (O_AF + O_BF)
__global__ __launch_bounds__(256) void out_gemm_tc2(
    const float* __restrict__ x, const float* __restrict__ zeta_b, float* __restrict__ out) {
    extern __shared__ float sm[];
    int n0 = blockIdx.x * 128, c0 = blockIdx.y * 128, b = blockIdx.z;
    const float* xb = x + (size_t)b * Cc * HWn;
    const float* ptb = g_Pt + (size_t)b * HWn * Kw;
    const float* wb = g_wneg + (size_t)b * Kw * Cc;
    int tid = threadIdx.x, wid = tid >> 5;
    int wm = wid & 1, wn = wid >> 1;

    FragC acc[4][2];
#pragma unroll
    for (int i = 0; i < 4; i++)
#pragma unroll
        for (int j = 0; j < 2; j++) wmma::fill_fragment(acc[i][j], 0.f);

    auto prefetch = [&](int ch, int st) {
        float* A = sm + st * O_STG;
        float* B = A + O_AF;
        int k0 = ch * 32;
#pragma unroll
        for (int j = 0; j < 4; j++) {                  // A rows n, contig k
            int f = tid + j * 256;
            int m = f >> 3, q = f & 7;
            int n = n0 + m;
            const float* src = (k0 < Cc)
                ? &xb[(size_t)n * Cc + k0 + q * 4]
                : &ptb[(size_t)n * Kw + (k0 - Cc) + q * 4];
            cpa16z(s2u(&A[m * 36 + q * 4]), src, n < HWn);
        }
#pragma unroll
        for (int j = 0; j < 4; j++) {                  // B rows r, contig c
            int f = tid + j * 256;
            int kk = f >> 5, c4 = f & 31;
            int r = k0 + kk;
            const float* src = (r < Cc) ? &g_zetaT[(size_t)r * Cc + c0 + c4 * 4]
                                        : &wb[(size_t)(r - Cc) * Cc + c0 + c4 * 4];
            cpa16(s2u(&B[kk * 132 + c4 * 4]), src);
        }
        CP_COMMIT();
    };

    prefetch(0, 0);
    const int NCH = 20;
    for (int ch = 0; ch < NCH; ch++) {
        if (ch + 1 < NCH) { prefetch(ch + 1, (ch + 1) & 1); CP_WAIT(1); }
        else CP_WAIT(0);
        __syncthreads();
        float* A = sm + (ch & 1) * O_STG;
        float* B = A + O_AF;
#pragma unroll
        for (int kk8 = 0; kk8 < 4; kk8++) {
            FragA a[4]; FragB bf[2];
#pragma unroll
            for (int i = 0; i < 4; i++)
                wmma::load_matrix_sync(a[i], &A[(wm * 64 + i * 16) * 36 + kk8 * 8], 36);
#pragma unroll
            for (int j = 0; j < 2; j++)
                wmma::load_matrix_sync(bf[j], &B[(kk8 * 8) * 132 + wn * 32 + j * 16], 132);
#pragma unroll
            for (int i = 0; i < 4; i++)
#pragma unroll
                for (int j = 0; j < 2; j++) wmma::mma_sync(acc[i][j], a[i], bf[j], acc[i][j]);
        }
        __syncthreads();
    }
    float* Cs = sm;                                     // [128][132]
#pragma unroll
    for (int i = 0; i < 4; i++)
#pragma unroll
        for (int j = 0; j < 2; j++)
            wmma::store_matrix_sync(&Cs[(wm * 64 + i * 16) * 132 + wn * 32 + j * 16],
                                    acc[i][j], 132, wmma::mem_row_major);
    __syncthreads();
    float* outb = out + (size_t)b * Cc * HWn;
#pragma unroll
    for (int j = 0; j < 16; j++) {
        int f = tid + j * 256;
        int m = f >> 5, c4 = f & 31;
        int n = n0 + m;
        if (n < HWn) {
            int c = c0 + c4 * 4;
            size_t idx = (size_t)n * Cc + c;
            float4 xv = *(const float4*)&xb[idx];
            float4 bz = *(const float4*)&zeta_b[c];
            const float* s = &Cs[m * 132 + c4 * 4];
            float4 v;
            v.x = xv.x + fmaxf(s[0] + bz.x, 0.f);
            v.y = xv.y + fmaxf(s[1] + bz.y, 0.f);
            v.z = xv.z + fmaxf(s[2] + bz.z, 0.f);
            v.w = xv.w + fmaxf(s[3] + bz.w, 0.f);
            *(float4*)&outb[idx] = v;
        }
    }
}

// ---------------- launch ----------------
extern "C" void kernel_launch(void* const* d_in, const int* in_sizes, int n_in,
                              void* d_out, int out_size) {
    const float* x      = (const float*)d_in[0];
    const float* y      = (const float*)d_in[1];
    const float* phi_w  = (const float*)d_in[2];
    const float* phi_b  = (const float*)d_in[3];
    const float* rou_w  = (const float*)d_in[4];
    const float* rou_b  = (const float*)d_in[5];
    const float* zeta_w = (const float*)d_in[6];
    const float* zeta_b = (const float*)d_in[7];
    float* out = (float*)d_out;

    const int PHI_SMEM = 2 * PHI_STG * 4;   // 70656 B
    const int T_SMEM   = 2 * T_STG * 4;     // 54272 B
    const int O_SMEM   = 2 * O_STG * 4;     // 70656 B
    cudaFuncSetAttribute(phi_gemm_tc2, cudaFuncAttributeMaxDynamicSharedMemorySize, PHI_SMEM);
    cudaFuncSetAttribute(t_gemm_tc2,   cudaFuncAttributeMaxDynamicSharedMemorySize, T_SMEM);
    cudaFuncSetAttribute(out_gemm_tc2, cudaFuncAttributeMaxDynamicSharedMemorySize, O_SMEM);

    pool_kernel<<<Bsz * Cc, 256>>>(y);
    rou_kernel<<<Bsz, 128>>>(rou_w, rou_b);
    transpose_kernel<<<dim3(Cc / 32, Cc / 32), dim3(32, 8)>>>(zeta_w);
    phi_gemm_tc2<<<dim3(25, Bsz), 256, PHI_SMEM>>>(x, phi_w, phi_b);
    s_kernel<<<Bsz * Kw, 256>>>();
    d_kernel<<<dim3(13, Bsz), 256>>>();
    ps_kernel<<<dim3(98, 4, Bsz), dim3(32, 8)>>>();
    t_gemm_tc2<<<dim3(8, 2, Bsz), 256, T_SMEM>>>(x);
    w_gemm_kernel<<<dim3(Cc / 64, Kw / 64, Bsz), 256>>>();
    out_gemm_tc2<<<dim3(25, 4, Bsz), 256, O_SMEM>>>(x, zeta_b, out);
}

// round 9
// speedup vs baseline: 1.6705x; 1.1159x over previous
#include <cuda_runtime.h>
#include <cuda_bf16.h>
#include <mma.h>
#include <cstdint>
#include <cstddef>

using namespace nvcuda;

#define Bsz 16
#define Cc  512
#define HWn 3136
#define Kw  128

typedef wmma::fragment<wmma::matrix_a, 16, 16, 8, wmma::precision::tf32, wmma::row_major> FragA;
typedef wmma::fragment<wmma::matrix_b, 16, 16, 8, wmma::precision::tf32, wmma::row_major> FragB;
typedef wmma::fragment<wmma::accumulator, 16, 16, 8, float> FragC;

// ---------------- scratch ----------------
__device__ float g_phi[Bsz * Kw * HWn];     // relu(phi_w@x+b), [b][k][n]
__device__ float g_P[Bsz * Kw * HWn];       // P = phi*inv, [b][k][n]
__device__ float g_Pt[Bsz * HWn * Kw];      // P transposed, [b][n][k]
__device__ float g_inv[Bsz * HWn];
__device__ float g_s[Bsz * Kw];
__device__ float g_rou[Bsz * Kw];
__device__ float g_pooled[Bsz * Cc];
__device__ float g_t[Bsz * Kw * Cc];
__device__ float g_t2[Bsz * Kw * Cc];
__device__ float g_wneg[Bsz * Kw * Cc];
__device__ float g_zetaT[Cc * Cc];

// ---------------- cp.async helpers ----------------
__device__ __forceinline__ uint32_t s2u(const void* p) {
    return (uint32_t)__cvta_generic_to_shared(p);
}
__device__ __forceinline__ void cpa16(uint32_t dst, const void* src) {
    asm volatile("cp.async.cg.shared.global [%0], [%1], 16;\n" :: "r"(dst), "l"(src));
}
__device__ __forceinline__ void cpa16z(uint32_t dst, const void* src, bool valid) {
    int sz = valid ? 16 : 0;
    asm volatile("cp.async.cg.shared.global [%0], [%1], 16, %2;\n" :: "r"(dst), "l"(src), "r"(sz));
}
#define CP_COMMIT() asm volatile("cp.async.commit_group;\n")
#define CP_WAIT(n)  asm volatile("cp.async.wait_group %0;\n" :: "n"(n))

// ---------------- 1) pooled ----------------
__global__ void pool_kernel(const float* __restrict__ y) {
    int bc = blockIdx.x;
    const float4* p4 = (const float4*)(y + (size_t)bc * HWn);
    float sum = 0.f;
    for (int i = threadIdx.x; i < HWn / 4; i += 256) {
        float4 v = p4[i];
        sum += v.x + v.y + v.z + v.w;
    }
    __shared__ float red[8];
    for (int o = 16; o; o >>= 1) sum += __shfl_down_sync(0xffffffffu, sum, o);
    if ((threadIdx.x & 31) == 0) red[threadIdx.x >> 5] = sum;
    __syncthreads();
    if (threadIdx.x < 8) {
        float v = red[threadIdx.x];
        for (int o = 4; o; o >>= 1) v += __shfl_down_sync(0xffu, v, o);
        if (threadIdx.x == 0) g_pooled[bc] = v / (float)HWn;
    }
}

// ---------------- 2) rou ----------------
__global__ void rou_kernel(const float* __restrict__ rou_w, const float* __restrict__ rou_b) {
    int b = blockIdx.x;
    __shared__ float sp[Cc];
    for (int i = threadIdx.x; i < Cc; i += 128) sp[i] = g_pooled[b * Cc + i];
    __syncthreads();
    int k = threadIdx.x;
    const float* wr = rou_w + k * Cc;
    float acc = rou_b[k];
#pragma unroll 8
    for (int c = 0; c < Cc; c++) acc += sp[c] * wr[c];
    g_rou[b * Kw + k] = 1.f / (1.f + __expf(-acc));
}

// ---------------- 3) zetaT ----------------
__global__ void transpose_kernel(const float* __restrict__ zw) {
    __shared__ float tile[32][33];
    int cx = blockIdx.x * 32 + threadIdx.x;
    int cy = blockIdx.y * 32;
    for (int j = 0; j < 32; j += 8)
        tile[threadIdx.y + j][threadIdx.x] = zw[(cy + threadIdx.y + j) * Cc + cx];
    __syncthreads();
    int ox = blockIdx.y * 32 + threadIdx.x;
    int oy = blockIdx.x * 32;
    for (int j = 0; j < 32; j += 8)
        g_zetaT[(oy + threadIdx.y + j) * Cc + ox] = tile[threadIdx.x][threadIdx.y + j];
}

// ---------------- 4) phi GEMM: TF32 TC, 3-stage cp.async, 2 CTA/SM ----------------
// M=128(k) x N=128(n), K=512. grid (25, B).
#define PHI_AF (128 * 36)
#define PHI_BF (32 * 132)
#define PHI_STG (PHI_AF + PHI_BF)
__global__ __launch_bounds__(256, 2) void phi_gemm_tc3(
    const float* __restrict__ x, const float* __restrict__ phi_w, const float* __restrict__ phi_b) {
    extern __shared__ float sm[];
    int b = blockIdx.y, n0 = blockIdx.x * 128;
    const float* xb = x + (size_t)b * Cc * HWn;
    int tid = threadIdx.x, wid = tid >> 5;
    int wm = wid & 1, wn = wid >> 1;

    FragC acc[4][2];
#pragma unroll
    for (int i = 0; i < 4; i++)
#pragma unroll
        for (int j = 0; j < 2; j++) wmma::fill_fragment(acc[i][j], 0.f);

    auto prefetch = [&](int ch) {
        float* A = sm + (ch % 3) * PHI_STG;
        float* B = A + PHI_AF;
        int k0 = ch * 32;
#pragma unroll
        for (int j = 0; j < 4; j++) {                  // A: phi_w 128x32
            int f = tid + j * 256;
            int m = f >> 3, q = f & 7;
            cpa16(s2u(&A[m * 36 + q * 4]), &phi_w[m * Cc + k0 + q * 4]);
        }
#pragma unroll
        for (int j = 0; j < 4; j++) {                  // B: x 32x128
            int f = tid + j * 256;
            int kk = f >> 5, n4 = f & 31;
            int n = n0 + n4 * 4;
            cpa16z(s2u(&B[kk * 132 + n4 * 4]), &xb[(size_t)(k0 + kk) * HWn + n], n < HWn);
        }
        CP_COMMIT();
    };

    prefetch(0);
    prefetch(1);
    const int NCH = Cc / 32;
    for (int ch = 0; ch < NCH; ch++) {
        if (ch < NCH - 1) CP_WAIT(1); else CP_WAIT(0);
        __syncthreads();
        if (ch + 2 < NCH) prefetch(ch + 2);
        float* A = sm + (ch % 3) * PHI_STG;
        float* B = A + PHI_AF;
#pragma unroll
        for (int kk8 = 0; kk8 < 4; kk8++) {
            FragA a[4]; FragB bf[2];
#pragma unroll
            for (int i = 0; i < 4; i++)
                wmma::load_matrix_sync(a[i], &A[(wm * 64 + i * 16) * 36 + kk8 * 8], 36);
#pragma unroll
            for (int j = 0; j < 2; j++)
                wmma::load_matrix_sync(bf[j], &B[(kk8 * 8) * 132 + wn * 32 + j * 16], 132);
#pragma unroll
            for (int i = 0; i < 4; i++)
#pragma unroll
                for (int j = 0; j < 2; j++) wmma::mma_sync(acc[i][j], a[i], bf[j], acc[i][j]);
        }
    }
    __syncthreads();
    float* Cs = sm;                                     // [128][132]
#pragma unroll
    for (int i = 0; i < 4; i++)
#pragma unroll
        for (int j = 0; j < 2; j++)
            wmma::store_matrix_sync(&Cs[(wm * 64 + i * 16) * 132 + wn * 32 + j * 16],
                                    acc[i][j], 132, wmma::mem_row_major);
    __syncthreads();
    float* outp = g_phi + (size_t)b * Kw * HWn;
#pragma unroll
    for (int j = 0; j < 16; j++) {
        int f = tid + j * 256;
        int m = f >> 5, c4 = f & 31;
        int n = n0 + c4 * 4;
        if (n < HWn) {
            float bias = phi_b[m];
            const float* s = &Cs[m * 132 + c4 * 4];
            float4 v;
            v.x = fmaxf(s[0] + bias, 0.f); v.y = fmaxf(s[1] + bias, 0.f);
            v.z = fmaxf(s[2] + bias, 0.f); v.w = fmaxf(s[3] + bias, 0.f);
            *(float4*)&outp[(size_t)m * HWn + n] = v;
        }
    }
}

// ---------------- 5) s ----------------
__global__ void s_kernel() {
    int bk = blockIdx.x;
    const float4* p4 = (const float4*)(g_phi + (size_t)bk * HWn);
    float sum = 0.f;
    for (int i = threadIdx.x; i < HWn / 4; i += 256) {
        float4 v = p4[i];
        sum += v.x + v.y + v.z + v.w;
    }
    __shared__ float red[8];
    for (int o = 16; o; o >>= 1) sum += __shfl_down_sync(0xffffffffu, sum, o);
    if ((threadIdx.x & 31) == 0) red[threadIdx.x >> 5] = sum;
    __syncthreads();
    if (threadIdx.x < 8) {
        float v = red[threadIdx.x];
        for (int o = 4; o; o >>= 1) v += __shfl_down_sync(0xffu, v, o);
        if (threadIdx.x == 0) g_s[bk] = v;
    }
}

// ---------------- 6) inv ----------------
__global__ void d_kernel() {
    int b = blockIdx.y;
    __shared__ float coef[Kw];
    if (threadIdx.x < Kw) coef[threadIdx.x] = g_rou[b * Kw + threadIdx.x] * g_s[b * Kw + threadIdx.x];
    __syncthreads();
    int n = blockIdx.x * 256 + threadIdx.x;
    if (n < HWn) {
        const float* p = g_phi + (size_t)b * Kw * HWn + n;
        float acc = 0.f;
#pragma unroll 8
        for (int k = 0; k < Kw; k++) acc += p[(size_t)k * HWn] * coef[k];
        g_inv[b * HWn + n] = rsqrtf(acc + 1e-8f);
    }
}

// ---------------- 6b) P in two layouts ----------------
__global__ void ps_kernel() {
    int n0 = blockIdx.x * 32, k0 = blockIdx.y * 32, b = blockIdx.z;
    const float* phib = g_phi + (size_t)b * Kw * HWn;
    float* pb = g_P + (size_t)b * Kw * HWn;
    __shared__ float tile[32][33];
    float inv = g_inv[b * HWn + n0 + threadIdx.x];
#pragma unroll
    for (int j = 0; j < 32; j += 8) {
        int k = k0 + threadIdx.y + j;
        float v = phib[(size_t)k * HWn + n0 + threadIdx.x] * inv;
        pb[(size_t)k * HWn + n0 + threadIdx.x] = v;
        tile[threadIdx.y + j][threadIdx.x] = v;
    }
    __syncthreads();
    float* ptb = g_Pt + (size_t)b * HWn * Kw;
#pragma unroll
    for (int j = 0; j < 32; j += 8) {
        int n = n0 + threadIdx.y + j;
        ptb[(size_t)n * Kw + k0 + threadIdx.x] = tile[threadIdx.x][threadIdx.y + j];
    }
}

// ---------------- 7) t GEMM: TF32 TC, 3-stage, split-K=2 ----------------
// M=128(k) x N=64(c), K=1568 per split. grid (8, 2, B).
#define T_AF (128 * 36)
#define T_BF (32 * 68)
#define T_STG (T_AF + T_BF)
__global__ __launch_bounds__(256, 2) void t_gemm_tc3(const float* __restrict__ x) {
    extern __shared__ float sm[];
    int c0 = blockIdx.x * 64, split = blockIdx.y, b = blockIdx.z;
    const float* pb = g_P + (size_t)b * Kw * HWn;
    const float* xb = x + (size_t)b * Cc * HWn;        // [HWn][Cc]
    int tid = threadIdx.x, wid = tid >> 5;
    int wm = wid & 3, wn = wid >> 2;
    int nbase = split * 1568;

    FragC acc[2][2];
#pragma unroll
    for (int i = 0; i < 2; i++)
#pragma unroll
        for (int j = 0; j < 2; j++) wmma::fill_fragment(acc[i][j], 0.f);

    auto prefetch = [&](int ch) {
        float* A = sm + (ch % 3) * T_STG;
        float* B = A + T_AF;
        int nb = nbase + ch * 32;
#pragma unroll
        for (int j = 0; j < 4; j++) {                  // A: P 128x32 (rows k, contig n)
            int f = tid + j * 256;
            int m = f >> 3, q = f & 7;
            cpa16(s2u(&A[m * 36 + q * 4]), &pb[(size_t)m * HWn + nb + q * 4]);
        }
#pragma unroll
        for (int j = 0; j < 2; j++) {                  // B: X2 32x64
            int f = tid + j * 256;
            int kk = f >> 4, c4 = f & 15;
            cpa16(s2u(&B[kk * 68 + c4 * 4]), &xb[(size_t)(nb + kk) * Cc + c0 + c4 * 4]);
        }
        CP_COMMIT();
    };

    prefetch(0);
    prefetch(1);
    const int NCH = 49;
    for (int ch = 0; ch < NCH; ch++) {
        if (ch < NCH - 1) CP_WAIT(1); else CP_WAIT(0);
        __syncthreads();
        if (ch + 2 < NCH) prefetch(ch + 2);
        float* A = sm + (ch % 3) * T_STG;
        float* B = A + T_AF;
#pragma unroll
        for (int kk8 = 0; kk8 < 4; kk8++) {
            FragA a[2]; FragB bf[2];
#pragma unroll
            for (int i = 0; i < 2; i++)
                wmma::load_matrix_sync(a[i], &A[(wm * 32 + i * 16) * 36 + kk8 * 8], 36);
#pragma unroll
            for (int j = 0; j < 2; j++)
                wmma::load_matrix_sync(bf[j], &B[(kk8 * 8) * 68 + wn * 32 + j * 16], 68);
#pragma unroll
            for (int i = 0; i < 2; i++)
#pragma unroll
                for (int j = 0; j < 2; j++) wmma::mma_sync(acc[i][j], a[i], bf[j], acc[i][j]);
        }
    }
    float* tb = (split ? g_t2 : g_t) + (size_t)b * Kw * Cc;
#pragma unroll
    for (int i = 0; i < 2; i++)
#pragma unroll
        for (int j = 0; j < 2; j++)
            wmma::store_matrix_sync(&tb[(size_t)(wm * 32 + i * 16) * Cc + c0 + wn * 32 + j * 16],
                                    acc[i][j], Cc, wmma::mem_row_major);
}

// ---------------- 8) w GEMM (SIMT, small) ----------------
__global__ __launch_bounds__(256) void w_gemm_kernel() {
    int b = blockIdx.z, m0 = blockIdx.y * 64, c0 = blockIdx.x * 64;
    const float* tb = g_t + (size_t)b * Kw * Cc;
    const float* tb2 = g_t2 + (size_t)b * Kw * Cc;
    __shared__ float As[16][64];
    __shared__ float Bs[16][64];
    float acc[4][4] = {};
    int tid = threadIdx.x, tx = tid & 15, ty = tid >> 4;

    for (int kk0 = 0; kk0 < Cc; kk0 += 16) {
        __syncthreads();
        {
            int m = tid >> 2, q = tid & 3;
            size_t off = (size_t)(m0 + m) * Cc + kk0 + q * 4;
            float4 v = *(const float4*)&tb[off];
            float4 v2 = *(const float4*)&tb2[off];
            As[q * 4 + 0][m] = v.x + v2.x; As[q * 4 + 1][m] = v.y + v2.y;
            As[q * 4 + 2][m] = v.z + v2.z; As[q * 4 + 3][m] = v.w + v2.w;
        }
        {
            int kk = tid >> 4, c4 = tid & 15;
            float4 v = *(const float4*)&g_zetaT[(size_t)(kk0 + kk) * Cc + c0 + c4 * 4];
            *(float4*)&Bs[kk][c4 * 4] = v;
        }
        __syncthreads();
#pragma unroll
        for (int kk = 0; kk < 16; kk++) {
            float4 a = *(float4*)&As[kk][ty * 4];
            float4 bb = *(float4*)&Bs[kk][tx * 4];
            float av[4] = {a.x, a.y, a.z, a.w};
            float bv[4] = {bb.x, bb.y, bb.z, bb.w};
#pragma unroll
            for (int i = 0; i < 4; i++)
#pragma unroll
                for (int jj = 0; jj < 4; jj++) acc[i][jj] += av[i] * bv[jj];
        }
    }
    float* wb = g_wneg + (size_t)b * Kw * Cc;
#pragma unroll
    for (int i = 0; i < 4; i++) {
        int m = m0 + ty * 4 + i;
        float r = -g_rou[b * Kw + m];
        float4 v = make_float4(r * acc[i][0], r * acc[i][1], r * acc[i][2], r * acc[i][3]);
        *(float4*)&wb[(size_t)m * Cc + c0 + tx * 4] = v;
    }
}

// ---------------- 9) fused out GEMM: TF32 TC, 3-stage ----------------
// M=128(n) x N=128(co), K=640. grid (25, 4, B).
#define O_AF (128 * 36)
#define O_BF (32 * 132)
#define O_STG (O_AF + O_BF)
__global__ __launch_bounds__(256, 2) void out_gemm_tc3(
    const float* __restrict__ x, const float* __restrict__ zeta_b, float* __restrict__ out) {
    extern __shared__ float sm[];
    int n0 = blockIdx.x * 128, c0 = blockIdx.y * 128, b = blockIdx.z;
    const float* xb = x + (size_t)b * Cc * HWn;
    const float* ptb = g_Pt + (size_t)b * HWn * Kw;
    const float* wb = g_wneg + (size_t)b * Kw * Cc;
    int tid = threadIdx.x, wid = tid >> 5;
    int wm = wid & 1, wn = wid >> 1;

    FragC acc[4][2];
#pragma unroll
    for (int i = 0; i < 4; i++)
#pragma unroll
        for (int j = 0; j < 2; j++) wmma::fill_fragment(acc[i][j], 0.f);

    auto prefetch = [&](int ch) {
        float* A = sm + (ch % 3) * O_STG;
        float* B = A + O_AF;
        int k0 = ch * 32;
#pragma unroll
        for (int j = 0; j < 4; j++) {                  // A rows n, contig k
            int f = tid + j * 256;
            int m = f >> 3, q = f & 7;
            int n = n0 + m;
            const float* src = (k0 < Cc)
                ? &xb[(size_t)n * Cc + k0 + q * 4]
                : &ptb[(size_t)n * Kw + (k0 - Cc) + q * 4];
            cpa16z(s2u(&A[m * 36 + q * 4]), src, n < HWn);
        }
#pragma unroll
        for (int j = 0; j < 4; j++) {                  // B rows r, contig c
            int f = tid + j * 256;
            int kk = f >> 5, c4 = f & 31;
            int r = k0 + kk;
            const float* src = (r < Cc) ? &g_zetaT[(size_t)r * Cc + c0 + c4 * 4]
                                        : &wb[(size_t)(r - Cc) * Cc + c0 + c4 * 4];
            cpa16(s2u(&B[kk * 132 + c4 * 4]), src);
        }
        CP_COMMIT();
    };

    prefetch(0);
    prefetch(1);
    const int NCH = 20;
    for (int ch = 0; ch < NCH; ch++) {
        if (ch < NCH - 1) CP_WAIT(1); else CP_WAIT(0);
        __syncthreads();
        if (ch + 2 < NCH) prefetch(ch + 2);
        float* A = sm + (ch % 3) * O_STG;
        float* B = A + O_AF;
#pragma unroll
        for (int kk8 = 0; kk8 < 4; kk8++) {
            FragA a[4]; FragB bf[2];
#pragma unroll
            for (int i = 0; i < 4; i++)
                wmma::load_matrix_sync(a[i], &A[(wm * 64 + i * 16) * 36 + kk8 * 8], 36);
#pragma unroll
            for (int j = 0; j < 2; j++)
                wmma::load_matrix_sync(bf[j], &B[(kk8 * 8) * 132 + wn * 32 + j * 16], 132);
#pragma unroll
            for (int i = 0; i < 4; i++)
#pragma unroll
                for (int j = 0; j < 2; j++) wmma::mma_sync(acc[i][j], a[i], bf[j], acc[i][j]);
        }
    }
    __syncthreads();
    float* Cs = sm;                                     // [128][132]
#pragma unroll
    for (int i = 0; i < 4; i++)
#pragma unroll
        for (int j = 0; j < 2; j++)
            wmma::store_matrix_sync(&Cs[(wm * 64 + i * 16) * 132 + wn * 32 + j * 16],
                                    acc[i][j], 132, wmma::mem_row_major);
    __syncthreads();
    float* outb = out + (size_t)b * Cc * HWn;
#pragma unroll
    for (int j = 0; j < 16; j++) {
        int f = tid + j * 256;
        int m = f >> 5, c4 = f & 31;
        int n = n0 + m;
        if (n < HWn) {
            int c = c0 + c4 * 4;
            size_t idx = (size_t)n * Cc + c;
            float4 xv = *(const float4*)&xb[idx];
            float4 bz = *(const float4*)&zeta_b[c];
            const float* s = &Cs[m * 132 + c4 * 4];
            float4 v;
            v.x = xv.x + fmaxf(s[0] + bz.x, 0.f);
            v.y = xv.y + fmaxf(s[1] + bz.y, 0.f);
            v.z = xv.z + fmaxf(s[2] + bz.z, 0.f);
            v.w = xv.w + fmaxf(s[3] + bz.w, 0.f);
            *(float4*)&outb[idx] = v;
        }
    }
}

// ---------------- launch ----------------
extern "C" void kernel_launch(void* const* d_in, const int* in_sizes, int n_in,
                              void* d_out, int out_size) {
    const float* x      = (const float*)d_in[0];
    const float* y      = (const float*)d_in[1];
    const float* phi_w  = (const float*)d_in[2];
    const float* phi_b  = (const float*)d_in[3];
    const float* rou_w  = (const float*)d_in[4];
    const float* rou_b  = (const float*)d_in[5];
    const float* zeta_w = (const float*)d_in[6];
    const float* zeta_b = (const float*)d_in[7];
    float* out = (float*)d_out;

    const int PHI_SMEM = 3 * PHI_STG * 4;   // 105984 B
    const int T_SMEM   = 3 * T_STG * 4;     // 81408 B
    const int O_SMEM   = 3 * O_STG * 4;     // 105984 B
    cudaFuncSetAttribute(phi_gemm_tc3, cudaFuncAttributeMaxDynamicSharedMemorySize, PHI_SMEM);
    cudaFuncSetAttribute(t_gemm_tc3,   cudaFuncAttributeMaxDynamicSharedMemorySize, T_SMEM);
    cudaFuncSetAttribute(out_gemm_tc3, cudaFuncAttributeMaxDynamicSharedMemorySize, O_SMEM);

    pool_kernel<<<Bsz * Cc, 256>>>(y);
    rou_kernel<<<Bsz, 128>>>(rou_w, rou_b);
    transpose_kernel<<<dim3(Cc / 32, Cc / 32), dim3(32, 8)>>>(zeta_w);
    phi_gemm_tc3<<<dim3(25, Bsz), 256, PHI_SMEM>>>(x, phi_w, phi_b);
    s_kernel<<<Bsz * Kw, 256>>>();
    d_kernel<<<dim3(13, Bsz), 256>>>();
    ps_kernel<<<dim3(98, 4, Bsz), dim3(32, 8)>>>();
    t_gemm_tc3<<<dim3(8, 2, Bsz), 256, T_SMEM>>>(x);
    w_gemm_kernel<<<dim3(Cc / 64, Kw / 64, Bsz), 256>>>();
    out_gemm_tc3<<<dim3(25, 4, Bsz), 256, O_SMEM>>>(x, zeta_b, out);
}

// round 12
// speedup vs baseline: 3.4729x; 2.0790x over previous
#include <cuda_runtime.h>
#include <cuda_fp16.h>
#include <mma.h>
#include <cstdint>
#include <cstddef>

using namespace nvcuda;

#define Bsz 16
#define Cc  512
#define HWn 3136
#define Kw  128

typedef wmma::fragment<wmma::matrix_a, 16, 16, 16, __half, wmma::row_major> HFragA;
typedef wmma::fragment<wmma::matrix_b, 16, 16, 16, __half, wmma::row_major> HFragB;
typedef wmma::fragment<wmma::matrix_b, 16, 16, 16, __half, wmma::col_major> HFragBc;
typedef wmma::fragment<wmma::accumulator, 16, 16, 16, float> HFragC;

// ---------------- scratch ----------------
__device__ __half g_phi[Bsz * Kw * HWn];    // relu(phi_w@x+b), [b][k][n], half
__device__ __half g_Ph[Bsz * Kw * HWn];     // P = phi*inv, [b][k][n], half
__device__ __half g_Pth[Bsz * HWn * Kw];    // P transposed, [b][n][k], half
__device__ __half g_xh[Bsz * Cc * HWn];     // x as half, flat (raw cast; [c][n] == [n_flat][c_flat])
__device__ __half g_phiwh[Kw * Cc];         // phi_w half
__device__ __half g_zwh[Cc * Cc];           // zeta_w half, [co][ci]
__device__ __half g_wTh[Bsz * Cc * Kw];     // wT[b][co][k] = -rou[k]*(t@zetaT)[k][co]
__device__ float g_inv[Bsz * HWn];
__device__ float g_s[Bsz * Kw];
__device__ float g_rou[Bsz * Kw];
__device__ float g_pooled[Bsz * Cc];
__device__ float g_t[Bsz * Kw * Cc];
__device__ float g_t2[Bsz * Kw * Cc];
__device__ float g_zetaT[Cc * Cc];          // zeta_w transposed (fp32, for w_gemm)

// ---------------- cp.async helpers ----------------
__device__ __forceinline__ uint32_t s2u(const void* p) {
    return (uint32_t)__cvta_generic_to_shared(p);
}
__device__ __forceinline__ void cpa16(uint32_t dst, const void* src) {
    asm volatile("cp.async.cg.shared.global [%0], [%1], 16;\n" :: "r"(dst), "l"(src));
}
__device__ __forceinline__ void cpa16z(uint32_t dst, const void* src, bool valid) {
    int sz = valid ? 16 : 0;
    asm volatile("cp.async.cg.shared.global [%0], [%1], 16, %2;\n" :: "r"(dst), "l"(src), "r"(sz));
}
#define CP_COMMIT() asm volatile("cp.async.commit_group;\n")
#define CP_WAIT(n)  asm volatile("cp.async.wait_group %0;\n" :: "n"(n))

// ---------------- 1) pooled ----------------
__global__ void pool_kernel(const float* __restrict__ y) {
    int bc = blockIdx.x;
    const float4* p4 = (const float4*)(y + (size_t)bc * HWn);
    float sum = 0.f;
    for (int i = threadIdx.x; i < HWn / 4; i += 256) {
        float4 v = p4[i];
        sum += v.x + v.y + v.z + v.w;
    }
    __shared__ float red[8];
    for (int o = 16; o; o >>= 1) sum += __shfl_down_sync(0xffffffffu, sum, o);
    if ((threadIdx.x & 31) == 0) red[threadIdx.x >> 5] = sum;
    __syncthreads();
    if (threadIdx.x < 8) {
        float v = red[threadIdx.x];
        for (int o = 4; o; o >>= 1) v += __shfl_down_sync(0xffu, v, o);
        if (threadIdx.x == 0) g_pooled[bc] = v / (float)HWn;
    }
}

// ---------------- 2) rou ----------------
__global__ void rou_kernel(const float* __restrict__ rou_w, const float* __restrict__ rou_b) {
    int b = blockIdx.x;
    __shared__ float sp[Cc];
    for (int i = threadIdx.x; i < Cc; i += 128) sp[i] = g_pooled[b * Cc + i];
    __syncthreads();
    int k = threadIdx.x;
    const float* wr = rou_w + k * Cc;
    float acc = rou_b[k];
#pragma unroll 8
    for (int c = 0; c < Cc; c++) acc += sp[c] * wr[c];
    g_rou[b * Kw + k] = 1.f / (1.f + __expf(-acc));
}

// ---------------- 3) zetaT (fp32, for w_gemm) ----------------
__global__ void transpose_kernel(const float* __restrict__ zw) {
    __shared__ float tile[32][33];
    int cx = blockIdx.x * 32 + threadIdx.x;
    int cy = blockIdx.y * 32;
    for (int j = 0; j < 32; j += 8)
        tile[threadIdx.y + j][threadIdx.x] = zw[(cy + threadIdx.y + j) * Cc + cx];
    __syncthreads();
    int ox = blockIdx.y * 32 + threadIdx.x;
    int oy = blockIdx.x * 32;
    for (int j = 0; j < 32; j += 8)
        g_zetaT[(oy + threadIdx.y + j) * Cc + ox] = tile[threadIdx.x][threadIdx.y + j];
}

// ---------------- 3b) cast weights to half ----------------
__global__ void castw_kernel(const float* __restrict__ phi_w, const float* __restrict__ zeta_w) {
    int i = blockIdx.x * 256 + threadIdx.x;
    if (i < Kw * Cc) g_phiwh[i] = __float2half(phi_w[i]);
    if (i < Cc * Cc) g_zwh[i] = __float2half(zeta_w[i]);
}

// ---------------- 3c) x -> half, FLAT raw cast (reshape is NOT a transpose) ----------------
__global__ void xh_kernel(const float* __restrict__ x) {
    size_t i = ((size_t)blockIdx.x * 256 + threadIdx.x) * 8;
    const size_t total = (size_t)Bsz * Cc * HWn;
    if (i < total) {
        float4 a = *(const float4*)&x[i];
        float4 b = *(const float4*)&x[i + 4];
        __half h[8];
        h[0] = __float2half(a.x); h[1] = __float2half(a.y);
        h[2] = __float2half(a.z); h[3] = __float2half(a.w);
        h[4] = __float2half(b.x); h[5] = __float2half(b.y);
        h[6] = __float2half(b.z); h[7] = __float2half(b.w);
        *(uint4*)&g_xh[i] = *(uint4*)h;
    }
}

// ---------------- 4) phi GEMM: FP16 wmma, 3-stage cp.async ----------------
// M=128(k) x N=128(n), K=512. grid (25, B).
#define PH_AS 40
#define PH_BS 136
#define PH_AF (128 * PH_AS)                 // halves
#define PH_BF (32 * PH_BS)
#define PH_STG (PH_AF + PH_BF)              // 9472 halves = 18944 B
__global__ __launch_bounds__(256, 2) void phi_gemm_h(const float* __restrict__ phi_b) {
    extern __shared__ char smraw[];
    __half* smh = (__half*)smraw;
    float* Cs = (float*)smraw;              // [128][132] overlay
    int b = blockIdx.y, n0 = blockIdx.x * 128;
    const __half* xhb = g_xh + (size_t)b * Cc * HWn;   // [c][n]
    int tid = threadIdx.x, wid = tid >> 5;
    int wm = wid & 3, wn = wid >> 2;        // warp tile 32(m) x 64(n)

    HFragC acc[2][4];
#pragma unroll
    for (int i = 0; i < 2; i++)
#pragma unroll
        for (int j = 0; j < 4; j++) wmma::fill_fragment(acc[i][j], 0.f);

    auto prefetch = [&](int ch) {
        __half* A = smh + (ch % 3) * PH_STG;
        __half* B = A + PH_AF;
        int k0 = ch * 32;
#pragma unroll
        for (int j = 0; j < 2; j++) {       // A: phi_w 128x32 half
            int f = tid + j * 256;
            int m = f >> 2, q = f & 3;
            cpa16(s2u(&A[m * PH_AS + q * 8]), &g_phiwh[m * Cc + k0 + q * 8]);
        }
#pragma unroll
        for (int j = 0; j < 2; j++) {       // B: x 32x128 half
            int f = tid + j * 256;
            int kk = f >> 4, n8 = f & 15;
            int n = n0 + n8 * 8;
            cpa16z(s2u(&B[kk * PH_BS + n8 * 8]), &xhb[(size_t)(k0 + kk) * HWn + n], n < HWn);
        }
        CP_COMMIT();
    };

    prefetch(0); prefetch(1);
    const int NCH = Cc / 32;
    for (int ch = 0; ch < NCH; ch++) {
        if (ch < NCH - 1) CP_WAIT(1); else CP_WAIT(0);
        __syncthreads();
        if (ch + 2 < NCH) prefetch(ch + 2);
        __half* A = smh + (ch % 3) * PH_STG;
        __half* B = A + PH_AF;
#pragma unroll
        for (int s = 0; s < 2; s++) {       // 2 x k16 steps
            HFragA a[2]; HFragB bf[4];
#pragma unroll
            for (int i = 0; i < 2; i++)
                wmma::load_matrix_sync(a[i], &A[(wm * 32 + i * 16) * PH_AS + s * 16], PH_AS);
#pragma unroll
            for (int j = 0; j < 4; j++)
                wmma::load_matrix_sync(bf[j], &B[(s * 16) * PH_BS + wn * 64 + j * 16], PH_BS);
#pragma unroll
            for (int i = 0; i < 2; i++)
#pragma unroll
                for (int j = 0; j < 4; j++) wmma::mma_sync(acc[i][j], a[i], bf[j], acc[i][j]);
        }
    }
    __syncthreads();
#pragma unroll
    for (int i = 0; i < 2; i++)
#pragma unroll
        for (int j = 0; j < 4; j++)
            wmma::store_matrix_sync(&Cs[(wm * 32 + i * 16) * 132 + wn * 64 + j * 16],
                                    acc[i][j], 132, wmma::mem_row_major);
    __syncthreads();
    __half* outp = g_phi + (size_t)b * Kw * HWn;
#pragma unroll
    for (int j = 0; j < 8; j++) {           // 8 halves per thread per iter
        int f = tid + j * 256;
        int m = f >> 4, c8 = f & 15;
        int n = n0 + c8 * 8;
        if (n < HWn) {
            float bias = phi_b[m];
            const float* s = &Cs[m * 132 + c8 * 8];
            __half h[8];
#pragma unroll
            for (int q = 0; q < 8; q++) h[q] = __float2half(fmaxf(s[q] + bias, 0.f));
            *(uint4*)&outp[(size_t)m * HWn + n] = *(uint4*)h;
        }
    }
}

// ---------------- 5) s[b,k] = sum_n phi ----------------
__global__ void s_kernel() {
    int bk = blockIdx.x;
    const __half2* p2 = (const __half2*)(g_phi + (size_t)bk * HWn);
    float sum = 0.f;
    for (int i = threadIdx.x; i < HWn / 2; i += 256) {
        float2 v = __half22float2(p2[i]);
        sum += v.x + v.y;
    }
    __shared__ float red[8];
    for (int o = 16; o; o >>= 1) sum += __shfl_down_sync(0xffffffffu, sum, o);
    if ((threadIdx.x & 31) == 0) red[threadIdx.x >> 5] = sum;
    __syncthreads();
    if (threadIdx.x < 8) {
        float v = red[threadIdx.x];
        for (int o = 4; o; o >>= 1) v += __shfl_down_sync(0xffu, v, o);
        if (threadIdx.x == 0) g_s[bk] = v;
    }
}

// ---------------- 6) inv ----------------
__global__ void d_kernel() {
    int b = blockIdx.y;
    __shared__ float coef[Kw];
    if (threadIdx.x < Kw) coef[threadIdx.x] = g_rou[b * Kw + threadIdx.x] * g_s[b * Kw + threadIdx.x];
    __syncthreads();
    int n = blockIdx.x * 256 + threadIdx.x;
    if (n < HWn) {
        const __half* p = g_phi + (size_t)b * Kw * HWn + n;
        float acc = 0.f;
#pragma unroll 8
        for (int k = 0; k < Kw; k++) acc += __half2float(p[(size_t)k * HWn]) * coef[k];
        g_inv[b * HWn + n] = rsqrtf(acc + 1e-8f);
    }
}

// ---------------- 6b) P in two half layouts ----------------
// grid (98, 4, B), block (32, 8)
__global__ void ps_kernel() {
    int n0 = blockIdx.x * 32, k0 = blockIdx.y * 32, b = blockIdx.z;
    const __half* phib = g_phi + (size_t)b * Kw * HWn;
    __half* phb = g_Ph + (size_t)b * Kw * HWn;
    __shared__ float tile[32][33];
    float inv = g_inv[b * HWn + n0 + threadIdx.x];
#pragma unroll
    for (int j = 0; j < 32; j += 8) {
        int k = k0 + threadIdx.y + j;
        float v = __half2float(phib[(size_t)k * HWn + n0 + threadIdx.x]) * inv;
        phb[(size_t)k * HWn + n0 + threadIdx.x] = __float2half(v);
        tile[threadIdx.y + j][threadIdx.x] = v;
    }
    __syncthreads();
    __half* ptb = g_Pth + (size_t)b * HWn * Kw;
#pragma unroll
    for (int j = 0; j < 32; j += 8) {
        int n = n0 + threadIdx.y + j;
        ptb[(size_t)n * Kw + k0 + threadIdx.x] = __float2half(tile[threadIdx.x][threadIdx.y + j]);
    }
}

// ---------------- 7) t GEMM: FP16 wmma, 3-stage, split-K=2 ----------------
// M=128(k) x N=64(c), K=1568 per split. grid (8, 2, B).
#define T_AS 40
#define T_BS 72
#define T_AF (128 * T_AS)
#define T_BF (32 * T_BS)
#define T_STG (T_AF + T_BF)                 // 7424 halves
__global__ __launch_bounds__(256, 2) void t_gemm_h() {
    extern __shared__ char smraw[];
    __half* smh = (__half*)smraw;
    int c0 = blockIdx.x * 64, split = blockIdx.y, b = blockIdx.z;
    const __half* phb = g_Ph + (size_t)b * Kw * HWn;
    const __half* xfh = g_xh + (size_t)b * Cc * HWn;   // flat: X2[n][c] = xfh[n*Cc+c]
    int tid = threadIdx.x, wid = tid >> 5;
    int wm = wid & 3, wn = wid >> 2;        // warp tile 32(k) x 32(c)
    int nbase = split * 1568;

    HFragC acc[2][2];
#pragma unroll
    for (int i = 0; i < 2; i++)
#pragma unroll
        for (int j = 0; j < 2; j++) wmma::fill_fragment(acc[i][j], 0.f);

    auto prefetch = [&](int ch) {
        __half* A = smh + (ch % 3) * T_STG;
        __half* B = A + T_AF;
        int nb = nbase + ch * 32;
#pragma unroll
        for (int j = 0; j < 2; j++) {       // A: P 128x32
            int f = tid + j * 256;
            int m = f >> 2, q = f & 3;
            cpa16(s2u(&A[m * T_AS + q * 8]), &phb[(size_t)m * HWn + nb + q * 8]);
        }
        {                                   // B: X2h 32x64
            int kk = tid >> 3, c8 = tid & 7;
            cpa16(s2u(&B[kk * T_BS + c8 * 8]), &xfh[(size_t)(nb + kk) * Cc + c0 + c8 * 8]);
        }
        CP_COMMIT();
    };

    prefetch(0); prefetch(1);
    const int NCH = 49;
    for (int ch = 0; ch < NCH; ch++) {
        if (ch < NCH - 1) CP_WAIT(1); else CP_WAIT(0);
        __syncthreads();
        if (ch + 2 < NCH) prefetch(ch + 2);
        __half* A = smh + (ch % 3) * T_STG;
        __half* B = A + T_AF;
#pragma unroll
        for (int s = 0; s < 2; s++) {
            HFragA a[2]; HFragB bf[2];
#pragma unroll
            for (int i = 0; i < 2; i++)
                wmma::load_matrix_sync(a[i], &A[(wm * 32 + i * 16) * T_AS + s * 16], T_AS);
#pragma unroll
            for (int j = 0; j < 2; j++)
                wmma::load_matrix_sync(bf[j], &B[(s * 16) * T_BS + wn * 32 + j * 16], T_BS);
#pragma unroll
            for (int i = 0; i < 2; i++)
#pragma unroll
                for (int j = 0; j < 2; j++) wmma::mma_sync(acc[i][j], a[i], bf[j], acc[i][j]);
        }
    }
    float* tb = (split ? g_t2 : g_t) + (size_t)b * Kw * Cc;
#pragma unroll
    for (int i = 0; i < 2; i++)
#pragma unroll
        for (int j = 0; j < 2; j++)
            wmma::store_matrix_sync(&tb[(size_t)(wm * 32 + i * 16) * Cc + c0 + wn * 32 + j * 16],
                                    acc[i][j], Cc, wmma::mem_row_major);
}

// ---------------- 8) w GEMM (SIMT fp32): wTh[co][k] = -rou[k]*((t0+t1)@zetaT)[k][co] ----------------
__global__ __launch_bounds__(256) void w_gemm_kernel() {
    int b = blockIdx.z, m0 = blockIdx.y * 64, c0 = blockIdx.x * 64;
    const float* tb = g_t + (size_t)b * Kw * Cc;
    const float* tb2 = g_t2 + (size_t)b * Kw * Cc;
    __shared__ float As[16][64];
    __shared__ float Bs[16][64];
    float acc[4][4] = {};
    int tid = threadIdx.x, tx = tid & 15, ty = tid >> 4;

    for (int kk0 = 0; kk0 < Cc; kk0 += 16) {
        __syncthreads();
        {
            int m = tid >> 2, q = tid & 3;
            size_t off = (size_t)(m0 + m) * Cc + kk0 + q * 4;
            float4 v = *(const float4*)&tb[off];
            float4 v2 = *(const float4*)&tb2[off];
            As[q * 4 + 0][m] = v.x + v2.x; As[q * 4 + 1][m] = v.y + v2.y;
            As[q * 4 + 2][m] = v.z + v2.z; As[q * 4 + 3][m] = v.w + v2.w;
        }
        {
            int kk = tid >> 4, c4 = tid & 15;
            float4 v = *(const float4*)&g_zetaT[(size_t)(kk0 + kk) * Cc + c0 + c4 * 4];
            *(float4*)&Bs[kk][c4 * 4] = v;
        }
        __syncthreads();
#pragma unroll
        for (int kk = 0; kk < 16; kk++) {
            float4 a = *(float4*)&As[kk][ty * 4];
            float4 bb = *(float4*)&Bs[kk][tx * 4];
            float av[4] = {a.x, a.y, a.z, a.w};
            float bv[4] = {bb.x, bb.y, bb.z, bb.w};
#pragma unroll
            for (int i = 0; i < 4; i++)
#pragma unroll
                for (int jj = 0; jj < 4; jj++) acc[i][jj] += av[i] * bv[jj];
        }
    }
    __half* wtb = g_wTh + (size_t)b * Cc * Kw;          // [co][k]
#pragma unroll
    for (int i = 0; i < 4; i++) {
        int m = m0 + ty * 4 + i;                        // k index
        float r = -g_rou[b * Kw + m];
#pragma unroll
        for (int jj = 0; jj < 4; jj++) {
            int c = c0 + tx * 4 + jj;                   // co index
            wtb[(size_t)c * Kw + m] = __float2half(r * acc[i][jj]);
        }
    }
}

// ---------------- 9) fused out GEMM: FP16 wmma, 3-stage ----------------
// D[n=128, co=128] = [X2|Pt][n,:] @ [zeta_w ; wT][co,:]^T, K=640. grid (25, 4, B).
#define O_AS 40
#define O_AF (128 * O_AS)
#define O_STG (2 * O_AF)                    // A + B, both 128x32 stride 40
__global__ __launch_bounds__(256, 2) void out_gemm_h(
    const float* __restrict__ x, const float* __restrict__ zeta_b, float* __restrict__ out) {
    extern __shared__ char smraw[];
    __half* smh = (__half*)smraw;
    float* Cs = (float*)smraw;              // [128][132] overlay
    int n0 = blockIdx.x * 128, c0 = blockIdx.y * 128, b = blockIdx.z;
    const float* xb = x + (size_t)b * Cc * HWn;
    const __half* xfh = g_xh + (size_t)b * Cc * HWn;   // flat: X2[n][c]
    const __half* pthb = g_Pth + (size_t)b * HWn * Kw;
    const __half* wthb = g_wTh + (size_t)b * Cc * Kw;
    int tid = threadIdx.x, wid = tid >> 5;
    int wm = wid & 3, wn = wid >> 2;        // warp tile 32(n) x 64(co)

    HFragC acc[2][4];
#pragma unroll
    for (int i = 0; i < 2; i++)
#pragma unroll
        for (int j = 0; j < 4; j++) wmma::fill_fragment(acc[i][j], 0.f);

    auto prefetch = [&](int ch) {
        __half* A = smh + (ch % 3) * O_STG;
        __half* B = A + O_AF;
        int k0 = ch * 32;
#pragma unroll
        for (int j = 0; j < 2; j++) {       // A: rows n, 128x32
            int f = tid + j * 256;
            int m = f >> 2, q = f & 3;
            int n = n0 + m;
            bool valid = n < HWn;
            int ns = valid ? n : (HWn - 1);
            const __half* src = (k0 < Cc)
                ? &xfh[(size_t)ns * Cc + k0 + q * 8]
                : &pthb[(size_t)ns * Kw + (k0 - Cc) + q * 8];
            cpa16z(s2u(&A[m * O_AS + q * 8]), src, valid);
        }
#pragma unroll
        for (int j = 0; j < 2; j++) {       // B: rows co, 128x32 (K-major -> col_major frags)
            int f = tid + j * 256;
            int m = f >> 2, q = f & 3;
            int co = c0 + m;
            const __half* src = (k0 < Cc)
                ? &g_zwh[(size_t)co * Cc + k0 + q * 8]
                : &wthb[(size_t)co * Kw + (k0 - Cc) + q * 8];
            cpa16(s2u(&B[m * O_AS + q * 8]), src);
        }
        CP_COMMIT();
    };

    prefetch(0); prefetch(1);
    const int NCH = 20;
    for (int ch = 0; ch < NCH; ch++) {
        if (ch < NCH - 1) CP_WAIT(1); else CP_WAIT(0);
        __syncthreads();
        if (ch + 2 < NCH) prefetch(ch + 2);
        __half* A = smh + (ch % 3) * O_STG;
        __half* B = A + O_AF;
#pragma unroll
        for (int s = 0; s < 2; s++) {
            HFragA a[2]; HFragBc bf[4];
#pragma unroll
            for (int i = 0; i < 2; i++)
                wmma::load_matrix_sync(a[i], &A[(wm * 32 + i * 16) * O_AS + s * 16], O_AS);
#pragma unroll
            for (int j = 0; j < 4; j++)
                wmma::load_matrix_sync(bf[j], &B[(wn * 64 + j * 16) * O_AS + s * 16], O_AS);
#pragma unroll
            for (int i = 0; i < 2; i++)
#pragma unroll
                for (int j = 0; j < 4; j++) wmma::mma_sync(acc[i][j], a[i], bf[j], acc[i][j]);
        }
    }
    __syncthreads();
#pragma unroll
    for (int i = 0; i < 2; i++)
#pragma unroll
        for (int j = 0; j < 4; j++)
            wmma::store_matrix_sync(&Cs[(wm * 32 + i * 16) * 132 + wn * 64 + j * 16],
                                    acc[i][j], 132, wmma::mem_row_major);
    __syncthreads();
    float* outb = out + (size_t)b * Cc * HWn;
#pragma unroll
    for (int j = 0; j < 16; j++) {
        int f = tid + j * 256;
        int m = f >> 5, c4 = f & 31;
        int n = n0 + m;
        if (n < HWn) {
            int c = c0 + c4 * 4;
            size_t idx = (size_t)n * Cc + c;
            float4 xv = *(const float4*)&xb[idx];
            float4 bz = *(const float4*)&zeta_b[c];
            const float* s = &Cs[m * 132 + c4 * 4];
            float4 v;
            v.x = xv.x + fmaxf(s[0] + bz.x, 0.f);
            v.y = xv.y + fmaxf(s[1] + bz.y, 0.f);
            v.z = xv.z + fmaxf(s[2] + bz.z, 0.f);
            v.w = xv.w + fmaxf(s[3] + bz.w, 0.f);
            *(float4*)&outb[idx] = v;
        }
    }
}

// ---------------- launch ----------------
extern "C" void kernel_launch(void* const* d_in, const int* in_sizes, int n_in,
                              void* d_out, int out_size) {
    const float* x      = (const float*)d_in[0];
    const float* y      = (const float*)d_in[1];
    const float* phi_w  = (const float*)d_in[2];
    const float* phi_b  = (const float*)d_in[3];
    const float* rou_w  = (const float*)d_in[4];
    const float* rou_b  = (const float*)d_in[5];
    const float* zeta_w = (const float*)d_in[6];
    const float* zeta_b = (const float*)d_in[7];
    float* out = (float*)d_out;

    const int PHI_SMEM = (3 * PH_STG * 2 > 128 * 132 * 4) ? 3 * PH_STG * 2 : 128 * 132 * 4; // 67584
    const int T_SMEM   = 3 * T_STG * 2;                                                     // 44544
    const int O_SMEM   = (3 * O_STG * 2 > 128 * 132 * 4) ? 3 * O_STG * 2 : 128 * 132 * 4;   // 67584
    cudaFuncSetAttribute(phi_gemm_h, cudaFuncAttributeMaxDynamicSharedMemorySize, PHI_SMEM);
    cudaFuncSetAttribute(t_gemm_h,   cudaFuncAttributeMaxDynamicSharedMemorySize, T_SMEM);
    cudaFuncSetAttribute(out_gemm_h, cudaFuncAttributeMaxDynamicSharedMemorySize, O_SMEM);

    pool_kernel<<<Bsz * Cc, 256>>>(y);
    rou_kernel<<<Bsz, 128>>>(rou_w, rou_b);
    transpose_kernel<<<dim3(Cc / 32, Cc / 32), dim3(32, 8)>>>(zeta_w);
    castw_kernel<<<(Cc * Cc + 255) / 256, 256>>>(phi_w, zeta_w);
    xh_kernel<<<(int)(((size_t)Bsz * Cc * HWn / 8 + 255) / 256), 256>>>(x);
    phi_gemm_h<<<dim3(25, Bsz), 256, PHI_SMEM>>>(phi_b);
    s_kernel<<<Bsz * Kw, 256>>>();
    d_kernel<<<dim3(13, Bsz), 256>>>();
    ps_kernel<<<dim3(98, 4, Bsz), dim3(32, 8)>>>();
    t_gemm_h<<<dim3(8, 2, Bsz), 256, T_SMEM>>>();
    w_gemm_kernel<<<dim3(Cc / 64, Kw / 64, Bsz), 256>>>();
    out_gemm_h<<<dim3(25, 4, Bsz), 256, O_SMEM>>>(x, zeta_b, out);
}

// round 13
// speedup vs baseline: 3.7425x; 1.0776x over previous
#include <cuda_runtime.h>
#include <cuda_fp16.h>
#include <mma.h>
#include <cstdint>
#include <cstddef>

using namespace nvcuda;

#define Bsz 16
#define Cc  512
#define HWn 3136
#define Kw  128

typedef wmma::fragment<wmma::matrix_a, 16, 16, 16, __half, wmma::row_major> HFragA;
typedef wmma::fragment<wmma::matrix_b, 16, 16, 16, __half, wmma::row_major> HFragB;
typedef wmma::fragment<wmma::matrix_b, 16, 16, 16, __half, wmma::col_major> HFragBc;
typedef wmma::fragment<wmma::accumulator, 16, 16, 16, float> HFragC;

// ---------------- scratch ----------------
__device__ __half g_phi[Bsz * Kw * HWn];    // relu(phi_w@x+b), [b][k][n], half
__device__ __half g_Ph[Bsz * Kw * HWn];     // P = phi*inv, [b][k][n], half
__device__ __half g_Pth[Bsz * HWn * Kw];    // P transposed, [b][n][k], half
__device__ __half g_xh[Bsz * Cc * HWn];     // x as half, flat raw cast
__device__ __half g_phiwh[Kw * Cc];         // phi_w half
__device__ __half g_zwh[Cc * Cc];           // zeta_w half, [co][ci]
__device__ __half g_wTh[Bsz * Cc * Kw];     // wT[b][co][k] = -rou[k]*(t@zetaT)[k][co]
__device__ float g_inv[Bsz * HWn];
__device__ float g_s[Bsz * Kw];
__device__ float g_rou[Bsz * Kw];
__device__ float g_pooled[Bsz * Cc];
__device__ float g_t[Bsz * Kw * Cc];
__device__ float g_t2[Bsz * Kw * Cc];
__device__ float g_zetaT[Cc * Cc];          // zeta_w transposed (fp32, for w_gemm)

// ---------------- cp.async helpers ----------------
__device__ __forceinline__ uint32_t s2u(const void* p) {
    return (uint32_t)__cvta_generic_to_shared(p);
}
__device__ __forceinline__ void cpa16(uint32_t dst, const void* src) {
    asm volatile("cp.async.cg.shared.global [%0], [%1], 16;\n" :: "r"(dst), "l"(src));
}
__device__ __forceinline__ void cpa16z(uint32_t dst, const void* src, bool valid) {
    int sz = valid ? 16 : 0;
    asm volatile("cp.async.cg.shared.global [%0], [%1], 16, %2;\n" :: "r"(dst), "l"(src), "r"(sz));
}
#define CP_COMMIT() asm volatile("cp.async.commit_group;\n")
#define CP_WAIT(n)  asm volatile("cp.async.wait_group %0;\n" :: "n"(n))

// ---------------- 1) pooled ----------------
__global__ void pool_kernel(const float* __restrict__ y) {
    int bc = blockIdx.x;
    const float4* p4 = (const float4*)(y + (size_t)bc * HWn);
    float sum = 0.f;
    for (int i = threadIdx.x; i < HWn / 4; i += 256) {
        float4 v = p4[i];
        sum += v.x + v.y + v.z + v.w;
    }
    __shared__ float red[8];
    for (int o = 16; o; o >>= 1) sum += __shfl_down_sync(0xffffffffu, sum, o);
    if ((threadIdx.x & 31) == 0) red[threadIdx.x >> 5] = sum;
    __syncthreads();
    if (threadIdx.x < 8) {
        float v = red[threadIdx.x];
        for (int o = 4; o; o >>= 1) v += __shfl_down_sync(0xffu, v, o);
        if (threadIdx.x == 0) g_pooled[bc] = v / (float)HWn;
    }
}

// ---------------- 2) rou ----------------
__global__ void rou_kernel(const float* __restrict__ rou_w, const float* __restrict__ rou_b) {
    int b = blockIdx.x;
    __shared__ float sp[Cc];
    for (int i = threadIdx.x; i < Cc; i += 128) sp[i] = g_pooled[b * Cc + i];
    __syncthreads();
    int k = threadIdx.x;
    const float* wr = rou_w + k * Cc;
    float acc = rou_b[k];
#pragma unroll 8
    for (int c = 0; c < Cc; c++) acc += sp[c] * wr[c];
    g_rou[b * Kw + k] = 1.f / (1.f + __expf(-acc));
}

// ---------------- 3) zetaT (fp32, for w_gemm) ----------------
__global__ void transpose_kernel(const float* __restrict__ zw) {
    __shared__ float tile[32][33];
    int cx = blockIdx.x * 32 + threadIdx.x;
    int cy = blockIdx.y * 32;
    for (int j = 0; j < 32; j += 8)
        tile[threadIdx.y + j][threadIdx.x] = zw[(cy + threadIdx.y + j) * Cc + cx];
    __syncthreads();
    int ox = blockIdx.y * 32 + threadIdx.x;
    int oy = blockIdx.x * 32;
    for (int j = 0; j < 32; j += 8)
        g_zetaT[(oy + threadIdx.y + j) * Cc + ox] = tile[threadIdx.x][threadIdx.y + j];
}

// ---------------- 3b) cast weights to half ----------------
__global__ void castw_kernel(const float* __restrict__ phi_w, const float* __restrict__ zeta_w) {
    int i = blockIdx.x * 256 + threadIdx.x;
    if (i < Kw * Cc) g_phiwh[i] = __float2half(phi_w[i]);
    if (i < Cc * Cc) g_zwh[i] = __float2half(zeta_w[i]);
}

// ---------------- 3c) x -> half, FLAT raw cast ----------------
__global__ void xh_kernel(const float* __restrict__ x) {
    size_t i = ((size_t)blockIdx.x * 256 + threadIdx.x) * 8;
    const size_t total = (size_t)Bsz * Cc * HWn;
    if (i < total) {
        float4 a = *(const float4*)&x[i];
        float4 b = *(const float4*)&x[i + 4];
        __half h[8];
        h[0] = __float2half(a.x); h[1] = __float2half(a.y);
        h[2] = __float2half(a.z); h[3] = __float2half(a.w);
        h[4] = __float2half(b.x); h[5] = __float2half(b.y);
        h[6] = __float2half(b.z); h[7] = __float2half(b.w);
        *(uint4*)&g_xh[i] = *(uint4*)h;
    }
}

// ---------------- 4) phi GEMM: FP16 wmma, K-chunk 64, 2-stage ----------------
// M=128(k) x N=128(n), K=512. grid (25, B).
#define PH_AS 72
#define PH_BS 136
#define PH_AF (128 * PH_AS)                 // 9216 halves
#define PH_BF (64 * PH_BS)                  // 8704 halves
#define PH_STG (PH_AF + PH_BF)              // 17920 halves = 35840 B
__global__ __launch_bounds__(256, 2) void phi_gemm_h(const float* __restrict__ phi_b) {
    extern __shared__ char smraw[];
    __half* smh = (__half*)smraw;
    float* Cs = (float*)smraw;              // [128][132] overlay
    int b = blockIdx.y, n0 = blockIdx.x * 128;
    const __half* xhb = g_xh + (size_t)b * Cc * HWn;   // [c][n]
    int tid = threadIdx.x, wid = tid >> 5;
    int wm = wid & 3, wn = wid >> 2;        // warp tile 32(m) x 64(n)

    HFragC acc[2][4];
#pragma unroll
    for (int i = 0; i < 2; i++)
#pragma unroll
        for (int j = 0; j < 4; j++) wmma::fill_fragment(acc[i][j], 0.f);

    auto prefetch = [&](int ch) {
        __half* A = smh + (ch & 1) * PH_STG;
        __half* B = A + PH_AF;
        int k0 = ch * 64;
#pragma unroll
        for (int j = 0; j < 4; j++) {       // A: phi_w 128x64 half
            int f = tid + j * 256;
            int m = f >> 3, q = f & 7;
            cpa16(s2u(&A[m * PH_AS + q * 8]), &g_phiwh[m * Cc + k0 + q * 8]);
        }
#pragma unroll
        for (int j = 0; j < 4; j++) {       // B: x 64x128 half
            int f = tid + j * 256;
            int kk = f >> 4, n8 = f & 15;
            int n = n0 + n8 * 8;
            cpa16z(s2u(&B[kk * PH_BS + n8 * 8]), &xhb[(size_t)(k0 + kk) * HWn + n], n < HWn);
        }
        CP_COMMIT();
    };

    prefetch(0);
    const int NCH = Cc / 64;                // 8
    for (int ch = 0; ch < NCH; ch++) {
        __syncthreads();                    // all warps done with stage (ch+1)&1 (chunk ch-1)
        if (ch + 1 < NCH) { prefetch(ch + 1); CP_WAIT(1); }
        else CP_WAIT(0);
        __syncthreads();                    // chunk ch visible
        __half* A = smh + (ch & 1) * PH_STG;
        __half* B = A + PH_AF;
#pragma unroll
        for (int s = 0; s < 4; s++) {       // 4 x k16 steps
            HFragA a[2]; HFragB bf[4];
#pragma unroll
            for (int i = 0; i < 2; i++)
                wmma::load_matrix_sync(a[i], &A[(wm * 32 + i * 16) * PH_AS + s * 16], PH_AS);
#pragma unroll
            for (int j = 0; j < 4; j++)
                wmma::load_matrix_sync(bf[j], &B[(s * 16) * PH_BS + wn * 64 + j * 16], PH_BS);
#pragma unroll
            for (int i = 0; i < 2; i++)
#pragma unroll
                for (int j = 0; j < 4; j++) wmma::mma_sync(acc[i][j], a[i], bf[j], acc[i][j]);
        }
    }
    __syncthreads();
#pragma unroll
    for (int i = 0; i < 2; i++)
#pragma unroll
        for (int j = 0; j < 4; j++)
            wmma::store_matrix_sync(&Cs[(wm * 32 + i * 16) * 132 + wn * 64 + j * 16],
                                    acc[i][j], 132, wmma::mem_row_major);
    __syncthreads();
    __half* outp = g_phi + (size_t)b * Kw * HWn;
#pragma unroll
    for (int j = 0; j < 8; j++) {
        int f = tid + j * 256;
        int m = f >> 4, c8 = f & 15;
        int n = n0 + c8 * 8;
        if (n < HWn) {
            float bias = phi_b[m];
            const float* s = &Cs[m * 132 + c8 * 8];
            __half h[8];
#pragma unroll
            for (int q = 0; q < 8; q++) h[q] = __float2half(fmaxf(s[q] + bias, 0.f));
            *(uint4*)&outp[(size_t)m * HWn + n] = *(uint4*)h;
        }
    }
}

// ---------------- 5) s[b,k] = sum_n phi ----------------
__global__ void s_kernel() {
    int bk = blockIdx.x;
    const __half2* p2 = (const __half2*)(g_phi + (size_t)bk * HWn);
    float sum = 0.f;
    for (int i = threadIdx.x; i < HWn / 2; i += 256) {
        float2 v = __half22float2(p2[i]);
        sum += v.x + v.y;
    }
    __shared__ float red[8];
    for (int o = 16; o; o >>= 1) sum += __shfl_down_sync(0xffffffffu, sum, o);
    if ((threadIdx.x & 31) == 0) red[threadIdx.x >> 5] = sum;
    __syncthreads();
    if (threadIdx.x < 8) {
        float v = red[threadIdx.x];
        for (int o = 4; o; o >>= 1) v += __shfl_down_sync(0xffu, v, o);
        if (threadIdx.x == 0) g_s[bk] = v;
    }
}

// ---------------- 6) inv ----------------
__global__ void d_kernel() {
    int b = blockIdx.y;
    __shared__ float coef[Kw];
    if (threadIdx.x < Kw) coef[threadIdx.x] = g_rou[b * Kw + threadIdx.x] * g_s[b * Kw + threadIdx.x];
    __syncthreads();
    int n = blockIdx.x * 256 + threadIdx.x;
    if (n < HWn) {
        const __half* p = g_phi + (size_t)b * Kw * HWn + n;
        float acc = 0.f;
#pragma unroll 8
        for (int k = 0; k < Kw; k++) acc += __half2float(p[(size_t)k * HWn]) * coef[k];
        g_inv[b * HWn + n] = rsqrtf(acc + 1e-8f);
    }
}

// ---------------- 6b) P in two half layouts ----------------
__global__ void ps_kernel() {
    int n0 = blockIdx.x * 32, k0 = blockIdx.y * 32, b = blockIdx.z;
    const __half* phib = g_phi + (size_t)b * Kw * HWn;
    __half* phb = g_Ph + (size_t)b * Kw * HWn;
    __shared__ float tile[32][33];
    float inv = g_inv[b * HWn + n0 + threadIdx.x];
#pragma unroll
    for (int j = 0; j < 32; j += 8) {
        int k = k0 + threadIdx.y + j;
        float v = __half2float(phib[(size_t)k * HWn + n0 + threadIdx.x]) * inv;
        phb[(size_t)k * HWn + n0 + threadIdx.x] = __float2half(v);
        tile[threadIdx.y + j][threadIdx.x] = v;
    }
    __syncthreads();
    __half* ptb = g_Pth + (size_t)b * HWn * Kw;
#pragma unroll
    for (int j = 0; j < 32; j += 8) {
        int n = n0 + threadIdx.y + j;
        ptb[(size_t)n * Kw + k0 + threadIdx.x] = __float2half(tile[threadIdx.x][threadIdx.y + j]);
    }
}

// ---------------- 7) t GEMM: FP16 wmma, 3-stage, split-K=2 (chunk 32) ----------------
#define T_AS 40
#define T_BS 72
#define T_AF (128 * T_AS)
#define T_BF (32 * T_BS)
#define T_STG (T_AF + T_BF)                 // 7424 halves
__global__ __launch_bounds__(256, 2) void t_gemm_h() {
    extern __shared__ char smraw[];
    __half* smh = (__half*)smraw;
    int c0 = blockIdx.x * 64, split = blockIdx.y, b = blockIdx.z;
    const __half* phb = g_Ph + (size_t)b * Kw * HWn;
    const __half* xfh = g_xh + (size_t)b * Cc * HWn;   // flat: X2[n][c]
    int tid = threadIdx.x, wid = tid >> 5;
    int wm = wid & 3, wn = wid >> 2;        // warp tile 32(k) x 32(c)
    int nbase = split * 1568;

    HFragC acc[2][2];
#pragma unroll
    for (int i = 0; i < 2; i++)
#pragma unroll
        for (int j = 0; j < 2; j++) wmma::fill_fragment(acc[i][j], 0.f);

    auto prefetch = [&](int ch) {
        __half* A = smh + (ch % 3) * T_STG;
        __half* B = A + T_AF;
        int nb = nbase + ch * 32;
#pragma unroll
        for (int j = 0; j < 2; j++) {       // A: P 128x32
            int f = tid + j * 256;
            int m = f >> 2, q = f & 3;
            cpa16(s2u(&A[m * T_AS + q * 8]), &phb[(size_t)m * HWn + nb + q * 8]);
        }
        {                                   // B: X2h 32x64
            int kk = tid >> 3, c8 = tid & 7;
            cpa16(s2u(&B[kk * T_BS + c8 * 8]), &xfh[(size_t)(nb + kk) * Cc + c0 + c8 * 8]);
        }
        CP_COMMIT();
    };

    prefetch(0); prefetch(1);
    const int NCH = 49;
    for (int ch = 0; ch < NCH; ch++) {
        if (ch < NCH - 1) CP_WAIT(1); else CP_WAIT(0);
        __syncthreads();
        if (ch + 2 < NCH) prefetch(ch + 2);
        __half* A = smh + (ch % 3) * T_STG;
        __half* B = A + T_AF;
#pragma unroll
        for (int s = 0; s < 2; s++) {
            HFragA a[2]; HFragB bf[2];
#pragma unroll
            for (int i = 0; i < 2; i++)
                wmma::load_matrix_sync(a[i], &A[(wm * 32 + i * 16) * T_AS + s * 16], T_AS);
#pragma unroll
            for (int j = 0; j < 2; j++)
                wmma::load_matrix_sync(bf[j], &B[(s * 16) * T_BS + wn * 32 + j * 16], T_BS);
#pragma unroll
            for (int i = 0; i < 2; i++)
#pragma unroll
                for (int j = 0; j < 2; j++) wmma::mma_sync(acc[i][j], a[i], bf[j], acc[i][j]);
        }
    }
    float* tb = (split ? g_t2 : g_t) + (size_t)b * Kw * Cc;
#pragma unroll
    for (int i = 0; i < 2; i++)
#pragma unroll
        for (int j = 0; j < 2; j++)
            wmma::store_matrix_sync(&tb[(size_t)(wm * 32 + i * 16) * Cc + c0 + wn * 32 + j * 16],
                                    acc[i][j], Cc, wmma::mem_row_major);
}

// ---------------- 8) w GEMM (SIMT fp32): wTh[co][k] = -rou[k]*((t0+t1)@zetaT)[k][co] ----------------
__global__ __launch_bounds__(256) void w_gemm_kernel() {
    int b = blockIdx.z, m0 = blockIdx.y * 64, c0 = blockIdx.x * 64;
    const float* tb = g_t + (size_t)b * Kw * Cc;
    const float* tb2 = g_t2 + (size_t)b * Kw * Cc;
    __shared__ float As[16][64];
    __shared__ float Bs[16][64];
    float acc[4][4] = {};
    int tid = threadIdx.x, tx = tid & 15, ty = tid >> 4;

    for (int kk0 = 0; kk0 < Cc; kk0 += 16) {
        __syncthreads();
        {
            int m = tid >> 2, q = tid & 3;
            size_t off = (size_t)(m0 + m) * Cc + kk0 + q * 4;
            float4 v = *(const float4*)&tb[off];
            float4 v2 = *(const float4*)&tb2[off];
            As[q * 4 + 0][m] = v.x + v2.x; As[q * 4 + 1][m] = v.y + v2.y;
            As[q * 4 + 2][m] = v.z + v2.z; As[q * 4 + 3][m] = v.w + v2.w;
        }
        {
            int kk = tid >> 4, c4 = tid & 15;
            float4 v = *(const float4*)&g_zetaT[(size_t)(kk0 + kk) * Cc + c0 + c4 * 4];
            *(float4*)&Bs[kk][c4 * 4] = v;
        }
        __syncthreads();
#pragma unroll
        for (int kk = 0; kk < 16; kk++) {
            float4 a = *(float4*)&As[kk][ty * 4];
            float4 bb = *(float4*)&Bs[kk][tx * 4];
            float av[4] = {a.x, a.y, a.z, a.w};
            float bv[4] = {bb.x, bb.y, bb.z, bb.w};
#pragma unroll
            for (int i = 0; i < 4; i++)
#pragma unroll
                for (int jj = 0; jj < 4; jj++) acc[i][jj] += av[i] * bv[jj];
        }
    }
    __half* wtb = g_wTh + (size_t)b * Cc * Kw;          // [co][k]
#pragma unroll
    for (int i = 0; i < 4; i++) {
        int m = m0 + ty * 4 + i;                        // k index
        float r = -g_rou[b * Kw + m];
#pragma unroll
        for (int jj = 0; jj < 4; jj++) {
            int c = c0 + tx * 4 + jj;                   // co index
            wtb[(size_t)c * Kw + m] = __float2half(r * acc[i][jj]);
        }
    }
}

// ---------------- 9) fused out GEMM: FP16 wmma, K-chunk 64, 2-stage ----------------
// D[n=128, co=128] = [X2|Pt][n,:] @ [zeta_w ; wT][co,:]^T, K=640. grid (25, 4, B).
#define O_AS 72
#define O_AF (128 * O_AS)                   // 9216 halves
#define O_STG (2 * O_AF)                    // A + B per stage: 18432 halves = 36864 B
__global__ __launch_bounds__(256, 2) void out_gemm_h(
    const float* __restrict__ x, const float* __restrict__ zeta_b, float* __restrict__ out) {
    extern __shared__ char smraw[];
    __half* smh = (__half*)smraw;
    float* Cs = (float*)smraw;              // [128][132] overlay
    int n0 = blockIdx.x * 128, c0 = blockIdx.y * 128, b = blockIdx.z;
    const float* xb = x + (size_t)b * Cc * HWn;
    const __half* xfh = g_xh + (size_t)b * Cc * HWn;   // flat: X2[n][c]
    const __half* pthb = g_Pth + (size_t)b * HWn * Kw;
    const __half* wthb = g_wTh + (size_t)b * Cc * Kw;
    int tid = threadIdx.x, wid = tid >> 5;
    int wm = wid & 3, wn = wid >> 2;        // warp tile 32(n) x 64(co)

    HFragC acc[2][4];
#pragma unroll
    for (int i = 0; i < 2; i++)
#pragma unroll
        for (int j = 0; j < 4; j++) wmma::fill_fragment(acc[i][j], 0.f);

    auto prefetch = [&](int ch) {
        __half* A = smh + (ch & 1) * O_STG;
        __half* B = A + O_AF;
        int k0 = ch * 64;
#pragma unroll
        for (int j = 0; j < 4; j++) {       // A: rows n, 128x64
            int f = tid + j * 256;
            int m = f >> 3, q = f & 7;
            int n = n0 + m;
            bool valid = n < HWn;
            int ns = valid ? n : (HWn - 1);
            const __half* src = (k0 < Cc)
                ? &xfh[(size_t)ns * Cc + k0 + q * 8]
                : &pthb[(size_t)ns * Kw + (k0 - Cc) + q * 8];
            cpa16z(s2u(&A[m * O_AS + q * 8]), src, valid);
        }
#pragma unroll
        for (int j = 0; j < 4; j++) {       // B: rows co, 128x64 (K-major -> col_major frags)
            int f = tid + j * 256;
            int m = f >> 3, q = f & 7;
            int co = c0 + m;
            const __half* src = (k0 < Cc)
                ? &g_zwh[(size_t)co * Cc + k0 + q * 8]
                : &wthb[(size_t)co * Kw + (k0 - Cc) + q * 8];
            cpa16(s2u(&B[m * O_AS + q * 8]), src);
        }
        CP_COMMIT();
    };

    prefetch(0);
    const int NCH = 10;                     // 640 / 64
    for (int ch = 0; ch < NCH; ch++) {
        __syncthreads();                    // all warps done with the other stage
        if (ch + 1 < NCH) { prefetch(ch + 1); CP_WAIT(1); }
        else CP_WAIT(0);
        __syncthreads();                    // chunk ch visible
        __half* A = smh + (ch & 1) * O_STG;
        __half* B = A + O_AF;
#pragma unroll
        for (int s = 0; s < 4; s++) {
            HFragA a[2]; HFragBc bf[4];
#pragma unroll
            for (int i = 0; i < 2; i++)
                wmma::load_matrix_sync(a[i], &A[(wm * 32 + i * 16) * O_AS + s * 16], O_AS);
#pragma unroll
            for (int j = 0; j < 4; j++)
                wmma::load_matrix_sync(bf[j], &B[(wn * 64 + j * 16) * O_AS + s * 16], O_AS);
#pragma unroll
            for (int i = 0; i < 2; i++)
#pragma unroll
                for (int j = 0; j < 4; j++) wmma::mma_sync(acc[i][j], a[i], bf[j], acc[i][j]);
        }
    }
    __syncthreads();
#pragma unroll
    for (int i = 0; i < 2; i++)
#pragma unroll
        for (int j = 0; j < 4; j++)
            wmma::store_matrix_sync(&Cs[(wm * 32 + i * 16) * 132 + wn * 64 + j * 16],
                                    acc[i][j], 132, wmma::mem_row_major);
    __syncthreads();
    float* outb = out + (size_t)b * Cc * HWn;
#pragma unroll
    for (int j = 0; j < 16; j++) {
        int f = tid + j * 256;
        int m = f >> 5, c4 = f & 31;
        int n = n0 + m;
        if (n < HWn) {
            int c = c0 + c4 * 4;
            size_t idx = (size_t)n * Cc + c;
            float4 xv = *(const float4*)&xb[idx];
            float4 bz = *(const float4*)&zeta_b[c];
            const float* s = &Cs[m * 132 + c4 * 4];
            float4 v;
            v.x = xv.x + fmaxf(s[0] + bz.x, 0.f);
            v.y = xv.y + fmaxf(s[1] + bz.y, 0.f);
            v.z = xv.z + fmaxf(s[2] + bz.z, 0.f);
            v.w = xv.w + fmaxf(s[3] + bz.w, 0.f);
            *(float4*)&outb[idx] = v;
        }
    }
}

// ---------------- launch ----------------
extern "C" void kernel_launch(void* const* d_in, const int* in_sizes, int n_in,
                              void* d_out, int out_size) {
    const float* x      = (const float*)d_in[0];
    const float* y      = (const float*)d_in[1];
    const float* phi_w  = (const float*)d_in[2];
    const float* phi_b  = (const float*)d_in[3];
    const float* rou_w  = (const float*)d_in[4];
    const float* rou_b  = (const float*)d_in[5];
    const float* zeta_w = (const float*)d_in[6];
    const float* zeta_b = (const float*)d_in[7];
    float* out = (float*)d_out;

    const int PHI_SMEM = (2 * PH_STG * 2 > 128 * 132 * 4) ? 2 * PH_STG * 2 : 128 * 132 * 4; // 71680
    const int T_SMEM   = 3 * T_STG * 2;                                                     // 44544
    const int O_SMEM   = (2 * O_STG * 2 > 128 * 132 * 4) ? 2 * O_STG * 2 : 128 * 132 * 4;   // 73728
    cudaFuncSetAttribute(phi_gemm_h, cudaFuncAttributeMaxDynamicSharedMemorySize, PHI_SMEM);
    cudaFuncSetAttribute(t_gemm_h,   cudaFuncAttributeMaxDynamicSharedMemorySize, T_SMEM);
    cudaFuncSetAttribute(out_gemm_h, cudaFuncAttributeMaxDynamicSharedMemorySize, O_SMEM);

    pool_kernel<<<Bsz * Cc, 256>>>(y);
    rou_kernel<<<Bsz, 128>>>(rou_w, rou_b);
    transpose_kernel<<<dim3(Cc / 32, Cc / 32), dim3(32, 8)>>>(zeta_w);
    castw_kernel<<<(Cc * Cc + 255) / 256, 256>>>(phi_w, zeta_w);
    xh_kernel<<<(int)(((size_t)Bsz * Cc * HWn / 8 + 255) / 256), 256>>>(x);
    phi_gemm_h<<<dim3(25, Bsz), 256, PHI_SMEM>>>(phi_b);
    s_kernel<<<Bsz * Kw, 256>>>();
    d_kernel<<<dim3(13, Bsz), 256>>>();
    ps_kernel<<<dim3(98, 4, Bsz), dim3(32, 8)>>>();
    t_gemm_h<<<dim3(8, 2, Bsz), 256, T_SMEM>>>();
    w_gemm_kernel<<<dim3(Cc / 64, Kw / 64, Bsz), 256>>>();
    out_gemm_h<<<dim3(25, 4, Bsz), 256, O_SMEM>>>(x, zeta_b, out);
}